// round 6
// baseline (speedup 1.0000x reference)
#include <cuda_runtime.h>
#include <cuda_bf16.h>
#include <math.h>
#include <stdint.h>

#define HW 96
#define C0 720
#define M_TOT 18432
#define KC 6480                      // 9*720
#define NPROTO 20
#define BM 128
#define BN 144
#define BK 48
#define ROWB 112                     // 48 bf16 = 96B + 16B pad
#define A_PL (128*ROWB)              // 14336
#define B_PL (144*ROWB)              // 16128
#define STG (2*A_PL + 2*B_PL)        // 60928
#define NSTAGE 3
#define SMEM_DYN (NSTAGE*STG)        // 182784
#define NCHUNK 3264                  // 16B chunks per stage
#define NTHR 512
#define NSLOT 7

__device__ __nv_bfloat16 g_fh[M_TOT*C0], g_fl[M_TOT*C0];
__device__ __nv_bfloat16 g_wch[C0*KC], g_wcl[C0*KC];
__device__ __nv_bfloat16 g_w1h[C0*C0], g_w1l[C0*C0];
__device__ __nv_bfloat16 g_w2h[C0*C0], g_w2l[C0*C0];
__device__ __nv_bfloat16 g_ch[M_TOT*C0], g_cl[M_TOT*C0];
__device__ __nv_bfloat16 g_p1h[M_TOT*C0], g_p1l[M_TOT*C0];
__device__ float g_p2[M_TOT*C0];
__device__ float g_s1[C0], g_t1[C0], g_s2[C0], g_t2[C0];
__device__ float g_proton[NPROTO*C0];

__device__ __forceinline__ uint32_t smem_u32(const void* p){
    uint32_t a;
    asm("{ .reg .u64 t; cvta.to.shared.u64 t, %1; cvt.u32.u64 %0, t; }" : "=r"(a) : "l"(p));
    return a;
}
__device__ __forceinline__ void ldsm4(uint32_t* r, uint32_t a){
    asm volatile("ldmatrix.sync.aligned.m8n8.x4.shared.b16 {%0,%1,%2,%3}, [%4];"
        : "=r"(r[0]), "=r"(r[1]), "=r"(r[2]), "=r"(r[3]) : "r"(a));
}
__device__ __forceinline__ void ldsm2(uint32_t* r, uint32_t a){
    asm volatile("ldmatrix.sync.aligned.m8n8.x2.shared.b16 {%0,%1}, [%2];"
        : "=r"(r[0]), "=r"(r[1]) : "r"(a));
}
__device__ __forceinline__ void mma16816(float* c, const uint32_t* a, const uint32_t* b){
    asm volatile("mma.sync.aligned.m16n8k16.row.col.f32.bf16.bf16.f32 "
        "{%0,%1,%2,%3}, {%4,%5,%6,%7}, {%8,%9}, {%0,%1,%2,%3};"
        : "+f"(c[0]), "+f"(c[1]), "+f"(c[2]), "+f"(c[3])
        : "r"(a[0]), "r"(a[1]), "r"(a[2]), "r"(a[3]), "r"(b[0]), "r"(b[1]));
}
__device__ __forceinline__ void cpa16(uint32_t dst, const void* src, int sz){
    asm volatile("cp.async.cg.shared.global [%0], [%1], 16, %2;" :: "r"(dst), "l"(src), "r"(sz));
}
__device__ __forceinline__ void split_bf(float v, __nv_bfloat16& h, __nv_bfloat16& l){
    h = __float2bfloat16(v); l = __float2bfloat16(v - __bfloat162float(h));
}

// ---------------- concat + bilinear (align_corners=True) ----------------
__device__ __forceinline__ float bilerp(const float* __restrict__ s, int b, int Ci, int c, int S, int y, int x){
    float sc = (float)(S-1)/(float)(HW-1);
    float fy = y*sc, fx = x*sc;
    int y0 = (int)floorf(fy), x0 = (int)floorf(fx);
    int y1 = min(y0+1, S-1), x1 = min(x0+1, S-1);
    float wy = fy-y0, wx = fx-x0;
    const float* p = s + ((b*Ci+c)*S)*S;
    float v00=p[y0*S+x0], v01=p[y0*S+x1], v10=p[y1*S+x0], v11=p[y1*S+x1];
    return (v00*(1.f-wx)+v01*wx)*(1.f-wy) + (v10*(1.f-wx)+v11*wx)*wy;
}
__global__ void concat_kernel(const float* __restrict__ f1, const float* __restrict__ f2,
                              const float* __restrict__ f3, const float* __restrict__ f4){
    int idx = blockIdx.x*blockDim.x + threadIdx.x;
    if (idx >= M_TOT*C0) return;
    int c = idx % C0, m = idx / C0;
    int x = m%HW, y = (m/HW)%HW, b = m/(HW*HW);
    float v;
    if (c < 48)       v = f1[((b*48+c)*HW+y)*HW+x];
    else if (c < 144) v = bilerp(f2,b, 96,c-48, 48,y,x);
    else if (c < 336) v = bilerp(f3,b,192,c-144,24,y,x);
    else              v = bilerp(f4,b,384,c-336,12,y,x);
    __nv_bfloat16 h,l; split_bf(v,h,l);
    g_fh[idx]=h; g_fl[idx]=l;
}

// ---------------- prep ----------------
__global__ void prep_w3(const float* __restrict__ w){
    int idx = blockIdx.x*blockDim.x + threadIdx.x;
    if (idx >= C0*KC) return;
    int cout = idx / KC, k = idx % KC;
    int q = k / C0, cin = k % C0;
    float v = w[(cout*C0+cin)*9+q];
    __nv_bfloat16 h,l; split_bf(v,h,l);
    g_wch[idx]=h; g_wcl[idx]=l;
}
__global__ void prep_w1x1(const float* __restrict__ w1, const float* __restrict__ w2){
    int idx = blockIdx.x*blockDim.x + threadIdx.x;
    if (idx >= C0*C0) return;
    int cout = idx / C0, cin = idx % C0;
    __nv_bfloat16 h,l;
    split_bf(w1[cout*C0+cin],h,l); g_w1h[idx]=h; g_w1l[idx]=l;
    split_bf(w2[cout*C0+cin],h,l); g_w2h[idx]=h; g_w2l[idx]=l;
}
__global__ void prep_bn(const float* __restrict__ cb, const float* __restrict__ g1, const float* __restrict__ b1,
                        const float* __restrict__ rm1, const float* __restrict__ rv1, const float* __restrict__ pb1,
                        const float* __restrict__ g2, const float* __restrict__ b2,
                        const float* __restrict__ rm2, const float* __restrict__ rv2){
    int n = blockIdx.x*blockDim.x + threadIdx.x;
    if (n >= C0) return;
    float s1 = g1[n]*rsqrtf(rv1[n]+1e-5f);
    g_s1[n]=s1; g_t1[n]=(cb[n]-rm1[n])*s1+b1[n];
    float s2 = g2[n]*rsqrtf(rv2[n]+1e-5f);
    g_s2[n]=s2; g_t2[n]=(pb1[n]-rm2[n])*s2+b2[n];
}
__global__ void prep_proto(const float* __restrict__ pr){
    int w = blockIdx.x, lane = threadIdx.x & 31;
    float ss = 0.f;
    for (int i=lane;i<C0;i+=32){ float v=pr[w*C0+i]; ss+=v*v; }
    #pragma unroll
    for (int o=16;o;o>>=1) ss += __shfl_xor_sync(0xffffffffu, ss, o);
    float inv = 1.f/fmaxf(sqrtf(ss),1e-12f);
    for (int i=lane;i<C0;i+=32) g_proton[w*C0+i] = pr[w*C0+i]*inv;
}

// ---------------- bf16 mma.sync GEMM, 3xBF16 split, 3-stage cp.async, 512 thr ----------------
template<int MODE>
__global__ __launch_bounds__(NTHR,1) void gemm_mma(const float* __restrict__ pb2){
    extern __shared__ __align__(128) char smem[];
    const uint32_t su = smem_u32(smem);
    const int tid = threadIdx.x, lane = tid&31, wid = tid>>5;
    const int wm = wid&7, wn = wid>>3;          // 8 x 2 warp grid, warp tile 16x72
    const int m0 = blockIdx.y*BM, n0 = blockIdx.x*BN;
    const int Kdim = (MODE==0)? KC : C0;
    const int nIter = Kdim/BK;                  // 135 or 15

    const char* pAh = (const char*)((MODE==0)? g_fh : (MODE==1)? g_ch : g_p1h);
    const char* pAl = (const char*)((MODE==0)? g_fl : (MODE==1)? g_cl : g_p1l);
    const char* pBh = (const char*)((MODE==0)? g_wch : (MODE==1)? g_w1h : g_w2h);
    const char* pBl = (const char*)((MODE==0)? g_wcl : (MODE==1)? g_w1l : g_w2l);

    // per-slot precompute: NSLOT chunk slots per thread
    bool valid[NSLOT], isA[NSLOT], plane[NSLOT];
    int dstv[NSLOT], srcb[NSLOT], pyv[NSLOT], pxv[NSLOT], cch[NSLOT];
    #pragma unroll
    for (int p=0;p<NSLOT;p++){
        int i = tid + p*NTHR;
        valid[p] = (i < NCHUNK);
        isA[p]=false; plane[p]=false; dstv[p]=0; srcb[p]=0; pyv[p]=0; pxv[p]=0; cch[p]=0;
        if (!valid[p]) continue;
        if (i < 1536){
            isA[p] = true;
            int pl = (i>=768), j = i - pl*768;
            int r = j/6, c = j - 6*r;
            plane[p] = pl;
            dstv[p] = pl*A_PL + r*ROWB + c*16;
            cch[p] = c;
            int m = m0 + r;
            if (MODE==0){
                int b = m/(HW*HW), rm = m%(HW*HW);
                int y = rm/HW, x = rm%HW;
                pyv[p]=y; pxv[p]=x;
                srcb[p] = ((b*HW+y)*HW+x)*C0*2;   // pixel base bytes
            } else {
                srcb[p] = m*C0*2 + c*16;
            }
        } else {
            int ib = i-1536;
            int pl = (ib>=864), jb = ib - pl*864;
            int r = jb/6, c = jb - 6*r;
            plane[p] = pl;
            dstv[p] = 2*A_PL + pl*B_PL + r*ROWB + c*16;
            srcb[p] = (n0+r)*Kdim*2 + c*16;
        }
    }

    auto load_stage = [&](int it){
        uint32_t sb = su + (it % NSTAGE)*STG;
        int addK = it*BK*2;    // bytes
        #pragma unroll
        for (int p=0;p<NSLOT;p++){
            if (!valid[p]) continue;
            uint32_t dst = sb + dstv[p];
            if (isA[p]){
                if (MODE==0){
                    int k = it*BK + cch[p]*8;
                    int tap = k / C0;
                    int cin = k - tap*C0;
                    int dy = tap/3 - 1, dx = tap - (tap/3)*3 - 1;
                    int yy = pyv[p]+dy, xx = pxv[p]+dx;
                    int sz = (((unsigned)yy < HW) && ((unsigned)xx < HW)) ? 16 : 0;
                    const char* src = (plane[p]? pAl : pAh) + srcb[p] + ((dy*HW+dx)*C0 + cin)*2;
                    if (!sz) src = (const char*)pAh;
                    cpa16(dst, src, sz);
                } else {
                    cpa16(dst, (plane[p]? pAl : pAh) + srcb[p] + addK, 16);
                }
            } else {
                cpa16(dst, (plane[p]? pBl : pBh) + srcb[p] + addK, 16);
            }
        }
        asm volatile("cp.async.commit_group;" ::: "memory");
    };

    float acc[9][4];
    #pragma unroll
    for (int b=0;b<9;b++)
        #pragma unroll
        for (int c=0;c<4;c++) acc[b][c]=0.f;

    load_stage(0);
    load_stage(1);

    for (int it=0; it<nIter; ++it){
        if (it == nIter-1) asm volatile("cp.async.wait_group 0;" ::: "memory");
        else               asm volatile("cp.async.wait_group 1;" ::: "memory");
        __syncthreads();
        if (it+2 < nIter) load_stage(it+2);

        uint32_t sb = su + (it % NSTAGE)*STG;
        #pragma unroll
        for (int k16=0;k16<3;k16++){
            uint32_t ah[4], al[4];
            {
                uint32_t row = wm*16 + (lane&15);
                uint32_t ad = sb + row*ROWB + k16*32 + (lane>>4)*16;
                ldsm4(ah, ad);
                ldsm4(al, ad + A_PL);
            }
            #pragma unroll
            for (int np=0;np<5;np++){
                if (np<4){
                    uint32_t n = wn*72 + np*16 + (lane>>4)*8 + (lane&7);
                    uint32_t ad = sb + 2*A_PL + n*ROWB + k16*32 + ((lane>>3)&1)*16;
                    uint32_t bh[4], bl[4];
                    ldsm4(bh, ad);
                    ldsm4(bl, ad + B_PL);
                    #pragma unroll
                    for (int h=0;h<2;h++){
                        int nt = np*2+h;
                        mma16816(acc[nt], ah, bh+2*h);
                        mma16816(acc[nt], ah, bl+2*h);
                        mma16816(acc[nt], al, bh+2*h);
                    }
                } else {
                    uint32_t n = wn*72 + 64 + (lane&7);
                    uint32_t ad = sb + 2*A_PL + n*ROWB + k16*32 + ((lane>>3)&1)*16;
                    uint32_t bh[2], bl[2];
                    ldsm2(bh, ad);
                    ldsm2(bl, ad + B_PL);
                    mma16816(acc[8], ah, bh);
                    mma16816(acc[8], ah, bl);
                    mma16816(acc[8], al, bh);
                }
            }
        }
    }

    // ---- epilogue ----
    #pragma unroll
    for (int nt=0;nt<9;nt++){
        #pragma unroll
        for (int h=0;h<2;h++){
            int m = m0 + wm*16 + (lane>>2) + h*8;
            int n = n0 + wn*72 + nt*8 + (lane&3)*2;
            float v0 = acc[nt][2*h], v1 = acc[nt][2*h+1];
            if (MODE==2){
                float2 o; o.x = v0 + pb2[n]; o.y = v1 + pb2[n+1];
                *(float2*)(g_p2 + (long)m*C0 + n) = o;
            } else {
                const float* S = (MODE==0)? g_s1 : g_s2;
                const float* T = (MODE==0)? g_t1 : g_t2;
                __nv_bfloat16* Oh = (MODE==0)? g_ch : g_p1h;
                __nv_bfloat16* Ol = (MODE==0)? g_cl : g_p1l;
                float r0 = fmaxf(fmaf(v0, S[n],   T[n]),   0.f);
                float r1 = fmaxf(fmaf(v1, S[n+1], T[n+1]), 0.f);
                __nv_bfloat16 h0,l0,h1,l1;
                split_bf(r0,h0,l0); split_bf(r1,h1,l1);
                uint32_t ph = (uint32_t)__bfloat16_as_ushort(h0) | ((uint32_t)__bfloat16_as_ushort(h1)<<16);
                uint32_t plv = (uint32_t)__bfloat16_as_ushort(l0) | ((uint32_t)__bfloat16_as_ushort(l1)<<16);
                *(uint32_t*)(Oh + (long)m*C0 + n) = ph;
                *(uint32_t*)(Ol + (long)m*C0 + n) = plv;
            }
        }
    }
}

// ---------------- head ----------------
__global__ void head_kernel(const float* __restrict__ lng, const float* __restrict__ lnb,
                            const float* __restrict__ lmg, const float* __restrict__ lmb,
                            float* __restrict__ out){
    int warp = (blockIdx.x*blockDim.x + threadIdx.x)>>5;
    int lane = threadIdx.x & 31;
    if (warp >= M_TOT) return;
    const float* row = g_p2 + (long)warp*C0;
    float v[23]; float s=0.f, ss=0.f;
    #pragma unroll
    for (int i=0;i<23;i++){
        int idx = lane + i*32;
        float x = (idx<C0)? row[idx] : 0.f;
        v[i]=x; s+=x; ss+=x*x;
    }
    #pragma unroll
    for (int o=16;o;o>>=1){ s+=__shfl_xor_sync(0xffffffffu,s,o); ss+=__shfl_xor_sync(0xffffffffu,ss,o); }
    float mu = s/(float)C0;
    float rstd = rsqrtf(ss/(float)C0 - mu*mu + 1e-5f);
    float q = 0.f;
    #pragma unroll
    for (int i=0;i<23;i++){
        int idx = lane + i*32;
        float x = (idx<C0)? (v[i]-mu)*rstd*lng[idx]+lnb[idx] : 0.f;
        v[i]=x; q+=x*x;
    }
    #pragma unroll
    for (int o=16;o;o>>=1) q+=__shfl_xor_sync(0xffffffffu,q,o);
    float inv = 1.f/fmaxf(sqrtf(q),1e-12f);
    float mx0=-1e30f, mx1=-1e30f;
    for (int p=0;p<NPROTO;p++){
        float d=0.f;
        const float* pp = g_proton + p*C0;
        #pragma unroll
        for (int i=0;i<23;i++){
            int idx = lane + i*32;
            if (idx<C0) d += v[i]*pp[idx];
        }
        #pragma unroll
        for (int o=16;o;o>>=1) d+=__shfl_xor_sync(0xffffffffu,d,o);
        d *= inv;
        if (p<10) mx0=fmaxf(mx0,d); else mx1=fmaxf(mx1,d);
    }
    if (lane==0){
        float mu2 = 0.5f*(mx0+mx1);
        float d0 = mx0-mu2, d1 = mx1-mu2;
        float r2 = rsqrtf(0.5f*(d0*d0+d1*d1)+1e-5f);
        int m = warp;
        int x = m%HW, y = (m/HW)%HW, b = m/(HW*HW);
        out[((b*2+0)*HW+y)*HW+x] = d0*r2*lmg[0]+lmb[0];
        out[((b*2+1)*HW+y)*HW+x] = d1*r2*lmg[1]+lmb[1];
    }
}

extern "C" void kernel_launch(void* const* d_in, const int* in_sizes, int n_in,
                              void* d_out, int out_size){
    const float* feat1=(const float*)d_in[0];  const float* feat2=(const float*)d_in[1];
    const float* feat3=(const float*)d_in[2];  const float* feat4=(const float*)d_in[3];
    const float* cls_w=(const float*)d_in[4];  const float* cls_b=(const float*)d_in[5];
    const float* cbn_g=(const float*)d_in[6];  const float* cbn_b=(const float*)d_in[7];
    const float* cbn_rm=(const float*)d_in[8]; const float* cbn_rv=(const float*)d_in[9];
    const float* pw1=(const float*)d_in[10];   const float* pb1=(const float*)d_in[11];
    const float* pbn_g=(const float*)d_in[12]; const float* pbn_b=(const float*)d_in[13];
    const float* pbn_rm=(const float*)d_in[14];const float* pbn_rv=(const float*)d_in[15];
    const float* pw2=(const float*)d_in[16];   const float* pb2=(const float*)d_in[17];
    const float* lnf_g=(const float*)d_in[18]; const float* lnf_b=(const float*)d_in[19];
    const float* lnm_g=(const float*)d_in[20]; const float* lnm_b=(const float*)d_in[21];
    const float* protos=(const float*)d_in[22];
    float* out = (float*)d_out;

    static int smem_set = 0;
    if (!smem_set){
        cudaFuncSetAttribute(gemm_mma<0>, cudaFuncAttributeMaxDynamicSharedMemorySize, SMEM_DYN);
        cudaFuncSetAttribute(gemm_mma<1>, cudaFuncAttributeMaxDynamicSharedMemorySize, SMEM_DYN);
        cudaFuncSetAttribute(gemm_mma<2>, cudaFuncAttributeMaxDynamicSharedMemorySize, SMEM_DYN);
        smem_set = 1;
    }

    dim3 grid(5, M_TOT/BM);  // (5,144)
    // ncu captures the 4th launch -> make it the conv GEMM
    concat_kernel<<<(M_TOT*C0+255)/256, 256>>>(feat1, feat2, feat3, feat4);
    prep_w3<<<(C0*KC+255)/256, 256>>>(cls_w);
    prep_bn<<<3, 256>>>(cls_b, cbn_g, cbn_b, cbn_rm, cbn_rv, pb1, pbn_g, pbn_b, pbn_rm, pbn_rv);
    gemm_mma<0><<<grid, NTHR, SMEM_DYN>>>(nullptr);          // 4th: profiled
    prep_w1x1<<<(C0*C0+255)/256, 256>>>(pw1, pw2);
    prep_proto<<<NPROTO, 32>>>(protos);
    gemm_mma<1><<<grid, NTHR, SMEM_DYN>>>(nullptr);
    gemm_mma<2><<<grid, NTHR, SMEM_DYN>>>(pb2);
    head_kernel<<<(M_TOT*32+255)/256, 256>>>(lnf_g, lnf_b, lnm_g, lnm_b, out);
    (void)in_sizes; (void)n_in; (void)out_size;
}

// round 8
// speedup vs baseline: 1.0398x; 1.0398x over previous
#include <cuda_runtime.h>
#include <cuda_bf16.h>
#include <math.h>
#include <stdint.h>

#define HW 96
#define C0 720
#define M_TOT 18432
#define KC 6480                      // 9*720
#define NPROTO 20
#define BM 128
#define BN 144
#define BK 16
#define ROWB 48                      // 16 bf16 = 32B + 16B pad (conflict-free)
#define A_PL (128*ROWB)              // 6144
#define B_PL (144*ROWB)              // 6912
#define STG (2*A_PL + 2*B_PL)        // 26112
#define NSTAGE 4
#define SMEM_DYN (NSTAGE*STG)        // 104448  -> 2 CTAs/SM
#define NCHUNK 1088                  // A 2*128*2 + B 2*144*2
#define THR 256
#define NSLOT 5

__device__ __nv_bfloat16 g_fh[M_TOT*C0], g_fl[M_TOT*C0];
__device__ __nv_bfloat16 g_wch[C0*KC], g_wcl[C0*KC];
__device__ __nv_bfloat16 g_w1h[C0*C0], g_w1l[C0*C0];
__device__ __nv_bfloat16 g_w2h[C0*C0], g_w2l[C0*C0];
__device__ __nv_bfloat16 g_ch[M_TOT*C0], g_cl[M_TOT*C0];
__device__ __nv_bfloat16 g_p1h[M_TOT*C0], g_p1l[M_TOT*C0];
__device__ float g_p2[M_TOT*C0];
__device__ float g_s1[C0], g_t1[C0], g_s2[C0], g_t2[C0];
__device__ float g_proton[NPROTO*C0];

__device__ __forceinline__ uint32_t smem_u32(const void* p){
    uint32_t a;
    asm("{ .reg .u64 t; cvta.to.shared.u64 t, %1; cvt.u32.u64 %0, t; }" : "=r"(a) : "l"(p));
    return a;
}
__device__ __forceinline__ void ldsm4(uint32_t* r, uint32_t a){
    asm volatile("ldmatrix.sync.aligned.m8n8.x4.shared.b16 {%0,%1,%2,%3}, [%4];"
        : "=r"(r[0]), "=r"(r[1]), "=r"(r[2]), "=r"(r[3]) : "r"(a));
}
__device__ __forceinline__ void ldsm2(uint32_t* r, uint32_t a){
    asm volatile("ldmatrix.sync.aligned.m8n8.x2.shared.b16 {%0,%1}, [%2];"
        : "=r"(r[0]), "=r"(r[1]) : "r"(a));
}
__device__ __forceinline__ void mma16816(float* c, const uint32_t* a, const uint32_t* b){
    asm volatile("mma.sync.aligned.m16n8k16.row.col.f32.bf16.bf16.f32 "
        "{%0,%1,%2,%3}, {%4,%5,%6,%7}, {%8,%9}, {%0,%1,%2,%3};"
        : "+f"(c[0]), "+f"(c[1]), "+f"(c[2]), "+f"(c[3])
        : "r"(a[0]), "r"(a[1]), "r"(a[2]), "r"(a[3]), "r"(b[0]), "r"(b[1]));
}
__device__ __forceinline__ void cpa16(uint32_t dst, const void* src, int sz){
    asm volatile("cp.async.cg.shared.global [%0], [%1], 16, %2;" :: "r"(dst), "l"(src), "r"(sz));
}
__device__ __forceinline__ void split_bf(float v, __nv_bfloat16& h, __nv_bfloat16& l){
    h = __float2bfloat16(v); l = __float2bfloat16(v - __bfloat162float(h));
}

// ---------------- concat + bilinear (align_corners=True) ----------------
__device__ __forceinline__ float bilerp(const float* __restrict__ s, int b, int Ci, int c, int S, int y, int x){
    float sc = (float)(S-1)/(float)(HW-1);
    float fy = y*sc, fx = x*sc;
    int y0 = (int)floorf(fy), x0 = (int)floorf(fx);
    int y1 = min(y0+1, S-1), x1 = min(x0+1, S-1);
    float wy = fy-y0, wx = fx-x0;
    const float* p = s + ((b*Ci+c)*S)*S;
    float v00=p[y0*S+x0], v01=p[y0*S+x1], v10=p[y1*S+x0], v11=p[y1*S+x1];
    return (v00*(1.f-wx)+v01*wx)*(1.f-wy) + (v10*(1.f-wx)+v11*wx)*wy;
}
__global__ void concat_kernel(const float* __restrict__ f1, const float* __restrict__ f2,
                              const float* __restrict__ f3, const float* __restrict__ f4){
    int idx = blockIdx.x*blockDim.x + threadIdx.x;
    if (idx >= M_TOT*C0) return;
    int c = idx % C0, m = idx / C0;
    int x = m%HW, y = (m/HW)%HW, b = m/(HW*HW);
    float v;
    if (c < 48)       v = f1[((b*48+c)*HW+y)*HW+x];
    else if (c < 144) v = bilerp(f2,b, 96,c-48, 48,y,x);
    else if (c < 336) v = bilerp(f3,b,192,c-144,24,y,x);
    else              v = bilerp(f4,b,384,c-336,12,y,x);
    __nv_bfloat16 h,l; split_bf(v,h,l);
    g_fh[idx]=h; g_fl[idx]=l;
}

// ---------------- prep ----------------
__global__ void prep_w3(const float* __restrict__ w){
    int idx = blockIdx.x*blockDim.x + threadIdx.x;
    if (idx >= C0*KC) return;
    int cout = idx / KC, k = idx % KC;
    int q = k / C0, cin = k % C0;
    float v = w[(cout*C0+cin)*9+q];
    __nv_bfloat16 h,l; split_bf(v,h,l);
    g_wch[idx]=h; g_wcl[idx]=l;
}
__global__ void prep_w1x1(const float* __restrict__ w1, const float* __restrict__ w2){
    int idx = blockIdx.x*blockDim.x + threadIdx.x;
    if (idx >= C0*C0) return;
    int cout = idx / C0, cin = idx % C0;
    __nv_bfloat16 h,l;
    split_bf(w1[cout*C0+cin],h,l); g_w1h[idx]=h; g_w1l[idx]=l;
    split_bf(w2[cout*C0+cin],h,l); g_w2h[idx]=h; g_w2l[idx]=l;
}
__global__ void prep_bn(const float* __restrict__ cb, const float* __restrict__ g1, const float* __restrict__ b1,
                        const float* __restrict__ rm1, const float* __restrict__ rv1, const float* __restrict__ pb1,
                        const float* __restrict__ g2, const float* __restrict__ b2,
                        const float* __restrict__ rm2, const float* __restrict__ rv2){
    int n = blockIdx.x*blockDim.x + threadIdx.x;
    if (n >= C0) return;
    float s1 = g1[n]*rsqrtf(rv1[n]+1e-5f);
    g_s1[n]=s1; g_t1[n]=(cb[n]-rm1[n])*s1+b1[n];
    float s2 = g2[n]*rsqrtf(rv2[n]+1e-5f);
    g_s2[n]=s2; g_t2[n]=(pb1[n]-rm2[n])*s2+b2[n];
}
__global__ void prep_proto(const float* __restrict__ pr){
    int w = blockIdx.x, lane = threadIdx.x & 31;
    float ss = 0.f;
    for (int i=lane;i<C0;i+=32){ float v=pr[w*C0+i]; ss+=v*v; }
    #pragma unroll
    for (int o=16;o;o>>=1) ss += __shfl_xor_sync(0xffffffffu, ss, o);
    float inv = 1.f/fmaxf(sqrtf(ss),1e-12f);
    for (int i=lane;i<C0;i+=32) g_proton[w*C0+i] = pr[w*C0+i]*inv;
}

// ---------------- bf16 mma.sync GEMM, 3xBF16 split, 4-stage cp.async, 2 CTA/SM ----------------
template<int MODE>
__global__ __launch_bounds__(THR,2) void gemm_mma(const float* __restrict__ pb2){
    extern __shared__ __align__(128) char smem[];
    const uint32_t su = smem_u32(smem);
    const int tid = threadIdx.x, lane = tid&31, wid = tid>>5;
    const int wm = wid&3, wn = wid>>2;          // 4 x 2 warp grid, warp tile 32x72
    const int m0 = blockIdx.y*BM, n0 = blockIdx.x*BN;
    const int Kdim = (MODE==0)? KC : C0;
    const int nIter = Kdim/BK;                  // 405 or 45

    const char* pAh = (const char*)((MODE==0)? g_fh : (MODE==1)? g_ch : g_p1h);
    const char* pAl = (const char*)((MODE==0)? g_fl : (MODE==1)? g_cl : g_p1l);
    const char* pBh = (const char*)((MODE==0)? g_wch : (MODE==1)? g_w1h : g_w2h);
    const char* pBl = (const char*)((MODE==0)? g_wcl : (MODE==1)? g_w1l : g_w2l);

    // per-slot precompute: NSLOT chunk slots per thread (cheap shift-based decode)
    bool valid[NSLOT], isA[NSLOT], plane[NSLOT];
    int dstv[NSLOT], srcb[NSLOT], pyv[NSLOT], pxv[NSLOT], cch[NSLOT];
    #pragma unroll
    for (int p=0;p<NSLOT;p++){
        int i = tid + p*THR;
        valid[p] = (i < NCHUNK);
        isA[p]=false; plane[p]=false; dstv[p]=0; srcb[p]=0; pyv[p]=0; pxv[p]=0; cch[p]=0;
        if (!valid[p]) continue;
        if (i < 512){                 // A: 2 planes x 128 rows x 2 chunks
            isA[p] = true;
            int pl = i>>8, j = i&255;
            int r = j>>1, c = j&1;
            plane[p] = pl;
            dstv[p] = pl*A_PL + r*ROWB + c*16;
            cch[p] = c;
            int m = m0 + r;
            if (MODE==0){
                int b = m/(HW*HW), rm = m%(HW*HW);
                int y = rm/HW, x = rm%HW;
                pyv[p]=y; pxv[p]=x;
                srcb[p] = ((b*HW+y)*HW+x)*C0*2;   // pixel base bytes
            } else {
                srcb[p] = m*C0*2 + c*16;
            }
        } else {                      // B: 2 planes x 144 rows x 2 chunks
            int ib = i-512;
            int pl = (ib>=288), jb = ib - pl*288;
            int r = jb>>1, c = jb&1;
            plane[p] = pl;
            dstv[p] = 2*A_PL + pl*B_PL + r*ROWB + c*16;
            srcb[p] = (n0+r)*Kdim*2 + c*16;
        }
    }

    auto load_stage = [&](int it){
        uint32_t sb = su + (it & (NSTAGE-1))*STG;
        int addK = it*BK*2;    // bytes
        #pragma unroll
        for (int p=0;p<NSLOT;p++){
            if (!valid[p]) continue;
            uint32_t dst = sb + dstv[p];
            if (isA[p]){
                if (MODE==0){
                    int k = it*BK + cch[p]*8;
                    int tap = k / C0;
                    int cin = k - tap*C0;
                    int dy = tap/3 - 1, dx = tap - (tap/3)*3 - 1;
                    int yy = pyv[p]+dy, xx = pxv[p]+dx;
                    int sz = (((unsigned)yy < HW) && ((unsigned)xx < HW)) ? 16 : 0;
                    const char* src = (plane[p]? pAl : pAh) + srcb[p] + ((dy*HW+dx)*C0 + cin)*2;
                    if (!sz) src = (const char*)pAh;
                    cpa16(dst, src, sz);
                } else {
                    cpa16(dst, (plane[p]? pAl : pAh) + srcb[p] + addK, 16);
                }
            } else {
                cpa16(dst, (plane[p]? pBl : pBh) + srcb[p] + addK, 16);
            }
        }
        asm volatile("cp.async.commit_group;" ::: "memory");
    };

    float acc[2][9][4];
    #pragma unroll
    for (int a=0;a<2;a++)
        #pragma unroll
        for (int b=0;b<9;b++)
            #pragma unroll
            for (int c=0;c<4;c++) acc[a][b][c]=0.f;

    load_stage(0);
    load_stage(1);
    load_stage(2);

    for (int it=0; it<nIter; ++it){
        int rem = nIter-1-it;
        if (rem>=2)      asm volatile("cp.async.wait_group 2;" ::: "memory");
        else if (rem==1) asm volatile("cp.async.wait_group 1;" ::: "memory");
        else             asm volatile("cp.async.wait_group 0;" ::: "memory");
        __syncthreads();
        if (it+3 < nIter) load_stage(it+3);

        uint32_t sb = su + (it & (NSTAGE-1))*STG;
        uint32_t ah[2][4], al[2][4];
        #pragma unroll
        for (int mt=0;mt<2;mt++){
            uint32_t row = wm*32 + mt*16 + (lane&15);
            uint32_t ad = sb + row*ROWB + (lane>>4)*16;
            ldsm4(ah[mt], ad);
            ldsm4(al[mt], ad + A_PL);
        }
        #pragma unroll
        for (int np=0;np<5;np++){
            if (np<4){
                uint32_t n = wn*72 + np*16 + (lane>>4)*8 + (lane&7);
                uint32_t ad = sb + 2*A_PL + n*ROWB + ((lane>>3)&1)*16;
                uint32_t bh[4], bl[4];
                ldsm4(bh, ad);
                ldsm4(bl, ad + B_PL);
                #pragma unroll
                for (int h=0;h<2;h++){
                    int nt = np*2+h;
                    #pragma unroll
                    for (int mt=0;mt<2;mt++){
                        mma16816(acc[mt][nt], ah[mt], bh+2*h);
                        mma16816(acc[mt][nt], ah[mt], bl+2*h);
                        mma16816(acc[mt][nt], al[mt], bh+2*h);
                    }
                }
            } else {
                uint32_t n = wn*72 + 64 + (lane&7);
                uint32_t ad = sb + 2*A_PL + n*ROWB + ((lane>>3)&1)*16;
                uint32_t bh[2], bl[2];
                ldsm2(bh, ad);
                ldsm2(bl, ad + B_PL);
                #pragma unroll
                for (int mt=0;mt<2;mt++){
                    mma16816(acc[mt][8], ah[mt], bh);
                    mma16816(acc[mt][8], ah[mt], bl);
                    mma16816(acc[mt][8], al[mt], bh);
                }
            }
        }
    }

    // ---- epilogue ----
    #pragma unroll
    for (int mt=0;mt<2;mt++){
        #pragma unroll
        for (int nt=0;nt<9;nt++){
            #pragma unroll
            for (int h=0;h<2;h++){
                int m = m0 + wm*32 + mt*16 + (lane>>2) + h*8;
                int n = n0 + wn*72 + nt*8 + (lane&3)*2;
                float v0 = acc[mt][nt][2*h], v1 = acc[mt][nt][2*h+1];
                if (MODE==2){
                    float2 o; o.x = v0 + pb2[n]; o.y = v1 + pb2[n+1];
                    *(float2*)(g_p2 + (long)m*C0 + n) = o;
                } else {
                    const float* S = (MODE==0)? g_s1 : g_s2;
                    const float* T = (MODE==0)? g_t1 : g_t2;
                    __nv_bfloat16* Oh = (MODE==0)? g_ch : g_p1h;
                    __nv_bfloat16* Ol = (MODE==0)? g_cl : g_p1l;
                    float r0 = fmaxf(fmaf(v0, S[n],   T[n]),   0.f);
                    float r1 = fmaxf(fmaf(v1, S[n+1], T[n+1]), 0.f);
                    __nv_bfloat16 h0,l0,h1,l1;
                    split_bf(r0,h0,l0); split_bf(r1,h1,l1);
                    uint32_t ph = (uint32_t)__bfloat16_as_ushort(h0) | ((uint32_t)__bfloat16_as_ushort(h1)<<16);
                    uint32_t plv = (uint32_t)__bfloat16_as_ushort(l0) | ((uint32_t)__bfloat16_as_ushort(l1)<<16);
                    *(uint32_t*)(Oh + (long)m*C0 + n) = ph;
                    *(uint32_t*)(Ol + (long)m*C0 + n) = plv;
                }
            }
        }
    }
}

// ---------------- head ----------------
__global__ void head_kernel(const float* __restrict__ lng, const float* __restrict__ lnb,
                            const float* __restrict__ lmg, const float* __restrict__ lmb,
                            float* __restrict__ out){
    int warp = (blockIdx.x*blockDim.x + threadIdx.x)>>5;
    int lane = threadIdx.x & 31;
    if (warp >= M_TOT) return;
    const float* row = g_p2 + (long)warp*C0;
    float v[23]; float s=0.f, ss=0.f;
    #pragma unroll
    for (int i=0;i<23;i++){
        int idx = lane + i*32;
        float x = (idx<C0)? row[idx] : 0.f;
        v[i]=x; s+=x; ss+=x*x;
    }
    #pragma unroll
    for (int o=16;o;o>>=1){ s+=__shfl_xor_sync(0xffffffffu,s,o); ss+=__shfl_xor_sync(0xffffffffu,ss,o); }
    float mu = s/(float)C0;
    float rstd = rsqrtf(ss/(float)C0 - mu*mu + 1e-5f);
    float q = 0.f;
    #pragma unroll
    for (int i=0;i<23;i++){
        int idx = lane + i*32;
        float x = (idx<C0)? (v[i]-mu)*rstd*lng[idx]+lnb[idx] : 0.f;
        v[i]=x; q+=x*x;
    }
    #pragma unroll
    for (int o=16;o;o>>=1) q+=__shfl_xor_sync(0xffffffffu,q,o);
    float inv = 1.f/fmaxf(sqrtf(q),1e-12f);
    float mx0=-1e30f, mx1=-1e30f;
    for (int p=0;p<NPROTO;p++){
        float d=0.f;
        const float* pp = g_proton + p*C0;
        #pragma unroll
        for (int i=0;i<23;i++){
            int idx = lane + i*32;
            if (idx<C0) d += v[i]*pp[idx];
        }
        #pragma unroll
        for (int o=16;o;o>>=1) d+=__shfl_xor_sync(0xffffffffu,d,o);
        d *= inv;
        if (p<10) mx0=fmaxf(mx0,d); else mx1=fmaxf(mx1,d);
    }
    if (lane==0){
        float mu2 = 0.5f*(mx0+mx1);
        float d0 = mx0-mu2, d1 = mx1-mu2;
        float r2 = rsqrtf(0.5f*(d0*d0+d1*d1)+1e-5f);
        int m = warp;
        int x = m%HW, y = (m/HW)%HW, b = m/(HW*HW);
        out[((b*2+0)*HW+y)*HW+x] = d0*r2*lmg[0]+lmb[0];
        out[((b*2+1)*HW+y)*HW+x] = d1*r2*lmg[1]+lmb[1];
    }
}

extern "C" void kernel_launch(void* const* d_in, const int* in_sizes, int n_in,
                              void* d_out, int out_size){
    const float* feat1=(const float*)d_in[0];  const float* feat2=(const float*)d_in[1];
    const float* feat3=(const float*)d_in[2];  const float* feat4=(const float*)d_in[3];
    const float* cls_w=(const float*)d_in[4];  const float* cls_b=(const float*)d_in[5];
    const float* cbn_g=(const float*)d_in[6];  const float* cbn_b=(const float*)d_in[7];
    const float* cbn_rm=(const float*)d_in[8]; const float* cbn_rv=(const float*)d_in[9];
    const float* pw1=(const float*)d_in[10];   const float* pb1=(const float*)d_in[11];
    const float* pbn_g=(const float*)d_in[12]; const float* pbn_b=(const float*)d_in[13];
    const float* pbn_rm=(const float*)d_in[14];const float* pbn_rv=(const float*)d_in[15];
    const float* pw2=(const float*)d_in[16];   const float* pb2=(const float*)d_in[17];
    const float* lnf_g=(const float*)d_in[18]; const float* lnf_b=(const float*)d_in[19];
    const float* lnm_g=(const float*)d_in[20]; const float* lnm_b=(const float*)d_in[21];
    const float* protos=(const float*)d_in[22];
    float* out = (float*)d_out;

    static int smem_set = 0;
    if (!smem_set){
        cudaFuncSetAttribute(gemm_mma<0>, cudaFuncAttributeMaxDynamicSharedMemorySize, SMEM_DYN);
        cudaFuncSetAttribute(gemm_mma<1>, cudaFuncAttributeMaxDynamicSharedMemorySize, SMEM_DYN);
        cudaFuncSetAttribute(gemm_mma<2>, cudaFuncAttributeMaxDynamicSharedMemorySize, SMEM_DYN);
        smem_set = 1;
    }

    dim3 grid(5, M_TOT/BM);  // (5,144) = 720 CTAs
    // ncu captures the 4th launch -> keep it the conv GEMM
    concat_kernel<<<(M_TOT*C0+255)/256, 256>>>(feat1, feat2, feat3, feat4);
    prep_w3<<<(C0*KC+255)/256, 256>>>(cls_w);
    prep_bn<<<3, 256>>>(cls_b, cbn_g, cbn_b, cbn_rm, cbn_rv, pb1, pbn_g, pbn_b, pbn_rm, pbn_rv);
    gemm_mma<0><<<grid, THR, SMEM_DYN>>>(nullptr);          // 4th: profiled
    prep_w1x1<<<(C0*C0+255)/256, 256>>>(pw1, pw2);
    prep_proto<<<NPROTO, 32>>>(protos);
    gemm_mma<1><<<grid, THR, SMEM_DYN>>>(nullptr);
    gemm_mma<2><<<grid, THR, SMEM_DYN>>>(pb2);
    head_kernel<<<(M_TOT*32+255)/256, 256>>>(lnf_g, lnf_b, lnm_g, lnm_b, out);
    (void)in_sizes; (void)n_in; (void)out_size;
}

// round 12
// speedup vs baseline: 1.7036x; 1.6384x over previous
#include <cuda_runtime.h>
#include <cuda_bf16.h>
#include <math.h>
#include <stdint.h>

#define HW 96
#define C0 720
#define M_TOT 18432
#define NPROTO 20
#define NTILE 4608                   // 2*48*48 winograd tiles
#define TCH (NTILE*C0)               // one V/M plane
#define UCH (C0*C0)                  // one U plane
#define BM 128
#define BN 144
#define BK 16
#define ROWB 48
#define A_PL (128*ROWB)
#define B_PL (144*ROWB)
#define STG (2*A_PL + 2*B_PL)        // 26112
#define NSTAGE 4
#define SMEM_DYN (NSTAGE*STG)        // 104448 -> 2 CTA/SM
#define NCHUNK 1088
#define THR 256
#define NSLOT 5

__device__ float g_feats[M_TOT*C0];
__device__ __nv_bfloat16 g_Vh[16*TCH], g_Vl[16*TCH];
__device__ __nv_bfloat16 g_Uh[16*UCH], g_Ul[16*UCH];
__device__ float g_M[16L*TCH];
__device__ __nv_bfloat16 g_w1h[UCH], g_w1l[UCH];
__device__ __nv_bfloat16 g_w2h[UCH], g_w2l[UCH];
__device__ __nv_bfloat16 g_ch[M_TOT*C0], g_cl[M_TOT*C0];
__device__ __nv_bfloat16 g_p1h[M_TOT*C0], g_p1l[M_TOT*C0];
__device__ float g_p2[M_TOT*C0];
__device__ float g_s1[C0], g_t1[C0], g_s2[C0], g_t2[C0];
__device__ float g_proton[NPROTO*C0];

__device__ __forceinline__ uint32_t smem_u32(const void* p){
    uint32_t a;
    asm("{ .reg .u64 t; cvta.to.shared.u64 t, %1; cvt.u32.u64 %0, t; }" : "=r"(a) : "l"(p));
    return a;
}
__device__ __forceinline__ void ldsm4(uint32_t* r, uint32_t a){
    asm volatile("ldmatrix.sync.aligned.m8n8.x4.shared.b16 {%0,%1,%2,%3}, [%4];"
        : "=r"(r[0]), "=r"(r[1]), "=r"(r[2]), "=r"(r[3]) : "r"(a));
}
__device__ __forceinline__ void ldsm2(uint32_t* r, uint32_t a){
    asm volatile("ldmatrix.sync.aligned.m8n8.x2.shared.b16 {%0,%1}, [%2];"
        : "=r"(r[0]), "=r"(r[1]) : "r"(a));
}
__device__ __forceinline__ void mma16816(float* c, const uint32_t* a, const uint32_t* b){
    asm volatile("mma.sync.aligned.m16n8k16.row.col.f32.bf16.bf16.f32 "
        "{%0,%1,%2,%3}, {%4,%5,%6,%7}, {%8,%9}, {%0,%1,%2,%3};"
        : "+f"(c[0]), "+f"(c[1]), "+f"(c[2]), "+f"(c[3])
        : "r"(a[0]), "r"(a[1]), "r"(a[2]), "r"(a[3]), "r"(b[0]), "r"(b[1]));
}
__device__ __forceinline__ void cpa16(uint32_t dst, const void* src){
    asm volatile("cp.async.cg.shared.global [%0], [%1], 16;" :: "r"(dst), "l"(src));
}
__device__ __forceinline__ void split_bf(float v, __nv_bfloat16& h, __nv_bfloat16& l){
    h = __float2bfloat16(v); l = __float2bfloat16(v - __bfloat162float(h));
}

// ---------------- concat + bilinear (fp32 out) ----------------
__device__ __forceinline__ float bilerp(const float* __restrict__ s, int b, int Ci, int c, int S, int y, int x){
    float sc = (float)(S-1)/(float)(HW-1);
    float fy = y*sc, fx = x*sc;
    int y0 = (int)floorf(fy), x0 = (int)floorf(fx);
    int y1 = min(y0+1, S-1), x1 = min(x0+1, S-1);
    float wy = fy-y0, wx = fx-x0;
    const float* p = s + ((b*Ci+c)*S)*S;
    float v00=p[y0*S+x0], v01=p[y0*S+x1], v10=p[y1*S+x0], v11=p[y1*S+x1];
    return (v00*(1.f-wx)+v01*wx)*(1.f-wy) + (v10*(1.f-wx)+v11*wx)*wy;
}
__global__ void concat_kernel(const float* __restrict__ f1, const float* __restrict__ f2,
                              const float* __restrict__ f3, const float* __restrict__ f4){
    int idx = blockIdx.x*blockDim.x + threadIdx.x;
    if (idx >= M_TOT*C0) return;
    int c = idx % C0, m = idx / C0;
    int x = m%HW, y = (m/HW)%HW, b = m/(HW*HW);
    float v;
    if (c < 48)       v = f1[((b*48+c)*HW+y)*HW+x];
    else if (c < 144) v = bilerp(f2,b, 96,c-48, 48,y,x);
    else if (c < 336) v = bilerp(f3,b,192,c-144,24,y,x);
    else              v = bilerp(f4,b,384,c-336,12,y,x);
    g_feats[idx] = v;
}

// ---------------- winograd weight transform: U = G g G^T ----------------
__global__ void wino_w(const float* __restrict__ w){
    int idx = blockIdx.x*blockDim.x + threadIdx.x;
    if (idx >= UCH) return;
    int ci = idx % C0, co = idx / C0;
    float g[3][3];
    #pragma unroll
    for (int r=0;r<3;r++)
        #pragma unroll
        for (int c=0;c<3;c++) g[r][c] = w[(co*C0+ci)*9 + r*3 + c];
    float T[4][3];
    #pragma unroll
    for (int c=0;c<3;c++){
        T[0][c] = g[0][c];
        T[1][c] = 0.5f*(g[0][c]+g[1][c]+g[2][c]);
        T[2][c] = 0.5f*(g[0][c]-g[1][c]+g[2][c]);
        T[3][c] = g[2][c];
    }
    #pragma unroll
    for (int i=0;i<4;i++){
        float u0 = T[i][0];
        float u1 = 0.5f*(T[i][0]+T[i][1]+T[i][2]);
        float u2 = 0.5f*(T[i][0]-T[i][1]+T[i][2]);
        float u3 = T[i][2];
        float uu[4] = {u0,u1,u2,u3};
        #pragma unroll
        for (int j=0;j<4;j++){
            __nv_bfloat16 h,l; split_bf(uu[j],h,l);
            long o = (long)(i*4+j)*UCH + (long)co*C0 + ci;   // [u][co][ci]
            g_Uh[o]=h; g_Ul[o]=l;
        }
    }
}

// ---------------- winograd input transform: V = B^T d B ----------------
__global__ void wino_in(){
    int idx = blockIdx.x*blockDim.x + threadIdx.x;
    if (idx >= TCH) return;
    int ci = idx % C0, t = idx / C0;
    int b = t/2304, rem = t%2304, ty = rem/48, tx = rem%48;
    int iy = 2*ty-1, ix = 2*tx-1;
    float d[4][4];
    #pragma unroll
    for (int yy=0;yy<4;yy++){
        int y = iy+yy;
        #pragma unroll
        for (int xx=0;xx<4;xx++){
            int x = ix+xx;
            d[yy][xx] = (((unsigned)y<HW)&&((unsigned)x<HW)) ?
                g_feats[((long)((b*HW+y)*HW+x))*C0 + ci] : 0.f;
        }
    }
    float T[4][4];
    #pragma unroll
    for (int j=0;j<4;j++){
        T[0][j] = d[0][j]-d[2][j];
        T[1][j] = d[1][j]+d[2][j];
        T[2][j] = d[2][j]-d[1][j];
        T[3][j] = d[1][j]-d[3][j];
    }
    #pragma unroll
    for (int i=0;i<4;i++){
        float v0 = T[i][0]-T[i][2];
        float v1 = T[i][1]+T[i][2];
        float v2 = T[i][2]-T[i][1];
        float v3 = T[i][1]-T[i][3];
        float vv[4] = {v0,v1,v2,v3};
        #pragma unroll
        for (int j=0;j<4;j++){
            __nv_bfloat16 h,l; split_bf(vv[j],h,l);
            long o = (long)(i*4+j)*TCH + (long)t*C0 + ci;    // [u][t][ci]
            g_Vh[o]=h; g_Vl[o]=l;
        }
    }
}

// ---------------- unified K=720 GEMM, 3xBF16 split, 4-stage, 2 CTA/SM ----------------
// EPI 0: A=g_V*(plane z), B=g_U*(plane z) -> g_M fp32
// EPI 1: A=g_c*,  B=g_w1* -> BN2+ReLU -> g_p1*
// EPI 2: A=g_p1*, B=g_w2* -> +pb2 -> g_p2
template<int EPI>
__global__ __launch_bounds__(THR,2) void gemm_u(const float* __restrict__ pb2){
    extern __shared__ __align__(128) char smem[];
    const uint32_t su = smem_u32(smem);
    const int tid = threadIdx.x, lane = tid&31, wid = tid>>5;
    const int wm = wid&3, wn = wid>>2;
    const int m0 = blockIdx.y*BM, n0 = blockIdx.x*BN;
    const int nIter = C0/BK;   // 45

    // device-side pointer selection (host cannot pass __device__ symbol addrs)
    const char *pAh, *pAl, *pBh, *pBl;
    if (EPI==0){
        long zA = (long)blockIdx.z*TCH, zB = (long)blockIdx.z*UCH;
        pAh = (const char*)(g_Vh + zA); pAl = (const char*)(g_Vl + zA);
        pBh = (const char*)(g_Uh + zB); pBl = (const char*)(g_Ul + zB);
    } else if (EPI==1){
        pAh = (const char*)g_ch;  pAl = (const char*)g_cl;
        pBh = (const char*)g_w1h; pBl = (const char*)g_w1l;
    } else {
        pAh = (const char*)g_p1h; pAl = (const char*)g_p1l;
        pBh = (const char*)g_w2h; pBl = (const char*)g_w2l;
    }

    bool valid[NSLOT], isA[NSLOT], plane[NSLOT];
    int dstv[NSLOT], srcb[NSLOT];
    #pragma unroll
    for (int p=0;p<NSLOT;p++){
        int i = tid + p*THR;
        valid[p] = (i < NCHUNK);
        isA[p]=false; plane[p]=false; dstv[p]=0; srcb[p]=0;
        if (!valid[p]) continue;
        if (i < 512){
            isA[p] = true;
            int pl = i>>8, j = i&255, r = j>>1, c = j&1;
            plane[p] = pl;
            dstv[p] = pl*A_PL + r*ROWB + c*16;
            srcb[p] = (m0+r)*(C0*2) + c*16;
        } else {
            int ib = i-512;
            int pl = (ib>=288), jb = ib - pl*288, r = jb>>1, c = jb&1;
            plane[p] = pl;
            dstv[p] = 2*A_PL + pl*B_PL + r*ROWB + c*16;
            srcb[p] = (n0+r)*(C0*2) + c*16;
        }
    }

    auto load_stage = [&](int it){
        uint32_t sb = su + (it & (NSTAGE-1))*STG;
        int addK = it*BK*2;
        #pragma unroll
        for (int p=0;p<NSLOT;p++){
            if (!valid[p]) continue;
            const char* base = isA[p] ? (plane[p]? pAl : pAh) : (plane[p]? pBl : pBh);
            cpa16(sb + dstv[p], base + srcb[p] + addK);
        }
        asm volatile("cp.async.commit_group;" ::: "memory");
    };

    float acc[2][9][4];
    #pragma unroll
    for (int a=0;a<2;a++)
        #pragma unroll
        for (int b=0;b<9;b++)
            #pragma unroll
            for (int c=0;c<4;c++) acc[a][b][c]=0.f;

    load_stage(0); load_stage(1); load_stage(2);

    for (int it=0; it<nIter; ++it){
        int rem = nIter-1-it;
        if (rem>=2)      asm volatile("cp.async.wait_group 2;" ::: "memory");
        else if (rem==1) asm volatile("cp.async.wait_group 1;" ::: "memory");
        else             asm volatile("cp.async.wait_group 0;" ::: "memory");
        __syncthreads();
        if (it+3 < nIter) load_stage(it+3);

        uint32_t sb = su + (it & (NSTAGE-1))*STG;
        uint32_t ah[2][4], al[2][4];
        #pragma unroll
        for (int mt=0;mt<2;mt++){
            uint32_t row = wm*32 + mt*16 + (lane&15);
            uint32_t ad = sb + row*ROWB + (lane>>4)*16;
            ldsm4(ah[mt], ad);
            ldsm4(al[mt], ad + A_PL);
        }
        #pragma unroll
        for (int np=0;np<5;np++){
            if (np<4){
                uint32_t n = wn*72 + np*16 + (lane>>4)*8 + (lane&7);
                uint32_t ad = sb + 2*A_PL + n*ROWB + ((lane>>3)&1)*16;
                uint32_t bh[4], bl[4];
                ldsm4(bh, ad);
                ldsm4(bl, ad + B_PL);
                #pragma unroll
                for (int h=0;h<2;h++){
                    int nt = np*2+h;
                    #pragma unroll
                    for (int mt=0;mt<2;mt++){
                        mma16816(acc[mt][nt], ah[mt], bh+2*h);
                        mma16816(acc[mt][nt], ah[mt], bl+2*h);
                        mma16816(acc[mt][nt], al[mt], bh+2*h);
                    }
                }
            } else {
                uint32_t n = wn*72 + 64 + (lane&7);
                uint32_t ad = sb + 2*A_PL + n*ROWB + ((lane>>3)&1)*16;
                uint32_t bh[2], bl[2];
                ldsm2(bh, ad);
                ldsm2(bl, ad + B_PL);
                #pragma unroll
                for (int mt=0;mt<2;mt++){
                    mma16816(acc[mt][8], ah[mt], bh);
                    mma16816(acc[mt][8], ah[mt], bl);
                    mma16816(acc[mt][8], al[mt], bh);
                }
            }
        }
    }

    #pragma unroll
    for (int mt=0;mt<2;mt++){
        #pragma unroll
        for (int nt=0;nt<9;nt++){
            #pragma unroll
            for (int h=0;h<2;h++){
                int m = m0 + wm*32 + mt*16 + (lane>>2) + h*8;
                int n = n0 + wn*72 + nt*8 + (lane&3)*2;
                float v0 = acc[mt][nt][2*h], v1 = acc[mt][nt][2*h+1];
                if (EPI==0){
                    float2 o; o.x = v0; o.y = v1;
                    *(float2*)(g_M + (long)blockIdx.z*TCH + (long)m*C0 + n) = o;
                } else if (EPI==2){
                    float2 o; o.x = v0 + pb2[n]; o.y = v1 + pb2[n+1];
                    *(float2*)(g_p2 + (long)m*C0 + n) = o;
                } else {
                    float r0 = fmaxf(fmaf(v0, g_s2[n],   g_t2[n]),   0.f);
                    float r1 = fmaxf(fmaf(v1, g_s2[n+1], g_t2[n+1]), 0.f);
                    __nv_bfloat16 h0,l0,h1,l1;
                    split_bf(r0,h0,l0); split_bf(r1,h1,l1);
                    uint32_t ph = (uint32_t)__bfloat16_as_ushort(h0) | ((uint32_t)__bfloat16_as_ushort(h1)<<16);
                    uint32_t plv = (uint32_t)__bfloat16_as_ushort(l0) | ((uint32_t)__bfloat16_as_ushort(l1)<<16);
                    *(uint32_t*)(g_p1h + (long)m*C0 + n) = ph;
                    *(uint32_t*)(g_p1l + (long)m*C0 + n) = plv;
                }
            }
        }
    }
}

// ---------------- winograd output transform + BN1 + ReLU + split ----------------
__global__ void wino_out(){
    int idx = blockIdx.x*blockDim.x + threadIdx.x;
    if (idx >= TCH) return;
    int co = idx % C0, t = idx / C0;
    float m[16];
    #pragma unroll
    for (int u=0;u<16;u++) m[u] = g_M[(long)u*TCH + (long)t*C0 + co];
    float Z[2][4];
    #pragma unroll
    for (int j=0;j<4;j++){
        Z[0][j] = m[0*4+j]+m[1*4+j]+m[2*4+j];
        Z[1][j] = m[1*4+j]-m[2*4+j]-m[3*4+j];
    }
    float Y[2][2];
    #pragma unroll
    for (int i=0;i<2;i++){
        Y[i][0] = Z[i][0]+Z[i][1]+Z[i][2];
        Y[i][1] = Z[i][1]-Z[i][2]-Z[i][3];
    }
    int b = t/2304, rem = t%2304, ty = rem/48, tx = rem%48;
    float s = g_s1[co], tt = g_t1[co];
    #pragma unroll
    for (int i=0;i<2;i++)
        #pragma unroll
        for (int j=0;j<2;j++){
            float v = fmaxf(fmaf(Y[i][j], s, tt), 0.f);
            __nv_bfloat16 h,l; split_bf(v,h,l);
            long o = ((long)((b*HW + 2*ty+i)*HW + 2*tx+j))*C0 + co;
            g_ch[o]=h; g_cl[o]=l;
        }
}

// ---------------- prep ----------------
__global__ void prep_w1x1(const float* __restrict__ w1, const float* __restrict__ w2){
    int idx = blockIdx.x*blockDim.x + threadIdx.x;
    if (idx >= UCH) return;
    int cout = idx / C0, cin = idx % C0;
    __nv_bfloat16 h,l;
    split_bf(w1[cout*C0+cin],h,l); g_w1h[idx]=h; g_w1l[idx]=l;
    split_bf(w2[cout*C0+cin],h,l); g_w2h[idx]=h; g_w2l[idx]=l;
}
__global__ void prep_bn(const float* __restrict__ cb, const float* __restrict__ g1, const float* __restrict__ b1,
                        const float* __restrict__ rm1, const float* __restrict__ rv1, const float* __restrict__ pb1,
                        const float* __restrict__ g2, const float* __restrict__ b2,
                        const float* __restrict__ rm2, const float* __restrict__ rv2){
    int n = blockIdx.x*blockDim.x + threadIdx.x;
    if (n >= C0) return;
    float s1 = g1[n]*rsqrtf(rv1[n]+1e-5f);
    g_s1[n]=s1; g_t1[n]=(cb[n]-rm1[n])*s1+b1[n];
    float s2 = g2[n]*rsqrtf(rv2[n]+1e-5f);
    g_s2[n]=s2; g_t2[n]=(pb1[n]-rm2[n])*s2+b2[n];
}
__global__ void prep_proto(const float* __restrict__ pr){
    int w = blockIdx.x, lane = threadIdx.x & 31;
    float ss = 0.f;
    for (int i=lane;i<C0;i+=32){ float v=pr[w*C0+i]; ss+=v*v; }
    #pragma unroll
    for (int o=16;o;o>>=1) ss += __shfl_xor_sync(0xffffffffu, ss, o);
    float inv = 1.f/fmaxf(sqrtf(ss),1e-12f);
    for (int i=lane;i<C0;i+=32) g_proton[w*C0+i] = pr[w*C0+i]*inv;
}

// ---------------- head ----------------
__global__ void head_kernel(const float* __restrict__ lng, const float* __restrict__ lnb,
                            const float* __restrict__ lmg, const float* __restrict__ lmb,
                            float* __restrict__ out){
    int warp = (blockIdx.x*blockDim.x + threadIdx.x)>>5;
    int lane = threadIdx.x & 31;
    if (warp >= M_TOT) return;
    const float* row = g_p2 + (long)warp*C0;
    float v[23]; float s=0.f, ss=0.f;
    #pragma unroll
    for (int i=0;i<23;i++){
        int idx = lane + i*32;
        float x = (idx<C0)? row[idx] : 0.f;
        v[i]=x; s+=x; ss+=x*x;
    }
    #pragma unroll
    for (int o=16;o;o>>=1){ s+=__shfl_xor_sync(0xffffffffu,s,o); ss+=__shfl_xor_sync(0xffffffffu,ss,o); }
    float mu = s/(float)C0;
    float rstd = rsqrtf(ss/(float)C0 - mu*mu + 1e-5f);
    float q = 0.f;
    #pragma unroll
    for (int i=0;i<23;i++){
        int idx = lane + i*32;
        float x = (idx<C0)? (v[i]-mu)*rstd*lng[idx]+lnb[idx] : 0.f;
        v[i]=x; q+=x*x;
    }
    #pragma unroll
    for (int o=16;o;o>>=1) q+=__shfl_xor_sync(0xffffffffu,q,o);
    float inv = 1.f/fmaxf(sqrtf(q),1e-12f);
    float mx0=-1e30f, mx1=-1e30f;
    for (int p=0;p<NPROTO;p++){
        float d=0.f;
        const float* pp = g_proton + p*C0;
        #pragma unroll
        for (int i=0;i<23;i++){
            int idx = lane + i*32;
            if (idx<C0) d += v[i]*pp[idx];
        }
        #pragma unroll
        for (int o=16;o;o>>=1) d+=__shfl_xor_sync(0xffffffffu,d,o);
        d *= inv;
        if (p<10) mx0=fmaxf(mx0,d); else mx1=fmaxf(mx1,d);
    }
    if (lane==0){
        float mu2 = 0.5f*(mx0+mx1);
        float d0 = mx0-mu2, d1 = mx1-mu2;
        float r2 = rsqrtf(0.5f*(d0*d0+d1*d1)+1e-5f);
        int m = warp;
        int x = m%HW, y = (m/HW)%HW, b = m/(HW*HW);
        out[((b*2+0)*HW+y)*HW+x] = d0*r2*lmg[0]+lmb[0];
        out[((b*2+1)*HW+y)*HW+x] = d1*r2*lmg[1]+lmb[1];
    }
}

extern "C" void kernel_launch(void* const* d_in, const int* in_sizes, int n_in,
                              void* d_out, int out_size){
    const float* feat1=(const float*)d_in[0];  const float* feat2=(const float*)d_in[1];
    const float* feat3=(const float*)d_in[2];  const float* feat4=(const float*)d_in[3];
    const float* cls_w=(const float*)d_in[4];  const float* cls_b=(const float*)d_in[5];
    const float* cbn_g=(const float*)d_in[6];  const float* cbn_b=(const float*)d_in[7];
    const float* cbn_rm=(const float*)d_in[8]; const float* cbn_rv=(const float*)d_in[9];
    const float* pw1=(const float*)d_in[10];   const float* pb1=(const float*)d_in[11];
    const float* pbn_g=(const float*)d_in[12]; const float* pbn_b=(const float*)d_in[13];
    const float* pbn_rm=(const float*)d_in[14];const float* pbn_rv=(const float*)d_in[15];
    const float* pw2=(const float*)d_in[16];   const float* pb2=(const float*)d_in[17];
    const float* lnf_g=(const float*)d_in[18]; const float* lnf_b=(const float*)d_in[19];
    const float* lnm_g=(const float*)d_in[20]; const float* lnm_b=(const float*)d_in[21];
    const float* protos=(const float*)d_in[22];
    float* out = (float*)d_out;

    static int smem_set = 0;
    if (!smem_set){
        cudaFuncSetAttribute(gemm_u<0>, cudaFuncAttributeMaxDynamicSharedMemorySize, SMEM_DYN);
        cudaFuncSetAttribute(gemm_u<1>, cudaFuncAttributeMaxDynamicSharedMemorySize, SMEM_DYN);
        cudaFuncSetAttribute(gemm_u<2>, cudaFuncAttributeMaxDynamicSharedMemorySize, SMEM_DYN);
        smem_set = 1;
    }

    concat_kernel<<<(M_TOT*C0+255)/256, 256>>>(feat1, feat2, feat3, feat4);
    wino_w<<<(UCH+255)/256, 256>>>(cls_w);
    wino_in<<<(TCH+255)/256, 256>>>();
    dim3 gw(5, NTILE/BM, 16);   // (5,36,16)
    gemm_u<0><<<gw, THR, SMEM_DYN>>>(nullptr);   // 4th launch: profiled
    prep_bn<<<3, 256>>>(cls_b, cbn_g, cbn_b, cbn_rm, cbn_rv, pb1, pbn_g, pbn_b, pbn_rm, pbn_rv);
    wino_out<<<(TCH+255)/256, 256>>>();
    prep_w1x1<<<(UCH+255)/256, 256>>>(pw1, pw2);
    dim3 g1(5, M_TOT/BM, 1);    // (5,144)
    gemm_u<1><<<g1, THR, SMEM_DYN>>>(nullptr);
    gemm_u<2><<<g1, THR, SMEM_DYN>>>(pb2);
    prep_proto<<<NPROTO, 32>>>(protos);
    head_kernel<<<(M_TOT*32+255)/256, 256>>>(lnf_g, lnf_b, lnm_g, lnm_b, out);
    (void)in_sizes; (void)n_in; (void)out_size;
}

// round 13
// speedup vs baseline: 2.2047x; 1.2941x over previous
#include <cuda_runtime.h>
#include <cuda_bf16.h>
#include <cuda_fp16.h>
#include <math.h>
#include <stdint.h>

#define HW 96
#define C0 720
#define M_TOT 18432
#define NPROTO 20
#define NT4 1152                     // F(4x4) tiles: 2*24*24
#define TCH4 (NT4*C0)                // 829440, one V/M plane
#define UCH (C0*C0)                  // 518400, one U plane
#define BM 128
#define BN 144
#define BK 16
#define ROWB 48
#define A_PL (128*ROWB)
#define B_PL (144*ROWB)
#define STG (2*A_PL + 2*B_PL)        // 26112
#define NSTAGE 4
#define SMEM_DYN (NSTAGE*STG)        // 104448 -> 2 CTA/SM
#define NCHUNK 1088
#define THR 256
#define NSLOT 5

__device__ float g_feats[M_TOT*C0];
__device__ __half g_Vh[36L*TCH4], g_Vl[36L*TCH4];
__device__ __half g_Uh[36L*UCH], g_Ul[36L*UCH];
__device__ float g_M[36L*TCH4];
__device__ __nv_bfloat16 g_w1h[UCH], g_w1l[UCH];
__device__ __nv_bfloat16 g_w2h[UCH], g_w2l[UCH];
__device__ __nv_bfloat16 g_ch[M_TOT*C0], g_cl[M_TOT*C0];
__device__ __nv_bfloat16 g_p1h[M_TOT*C0], g_p1l[M_TOT*C0];
__device__ float g_p2[M_TOT*C0];
__device__ float g_s1[C0], g_t1[C0], g_s2[C0], g_t2[C0];
__device__ float g_proton[NPROTO*C0];

__device__ __forceinline__ uint32_t smem_u32(const void* p){
    uint32_t a;
    asm("{ .reg .u64 t; cvta.to.shared.u64 t, %1; cvt.u32.u64 %0, t; }" : "=r"(a) : "l"(p));
    return a;
}
__device__ __forceinline__ void ldsm4(uint32_t* r, uint32_t a){
    asm volatile("ldmatrix.sync.aligned.m8n8.x4.shared.b16 {%0,%1,%2,%3}, [%4];"
        : "=r"(r[0]), "=r"(r[1]), "=r"(r[2]), "=r"(r[3]) : "r"(a));
}
__device__ __forceinline__ void ldsm2(uint32_t* r, uint32_t a){
    asm volatile("ldmatrix.sync.aligned.m8n8.x2.shared.b16 {%0,%1}, [%2];"
        : "=r"(r[0]), "=r"(r[1]) : "r"(a));
}
__device__ __forceinline__ void mma_bf(float* c, const uint32_t* a, const uint32_t* b){
    asm volatile("mma.sync.aligned.m16n8k16.row.col.f32.bf16.bf16.f32 "
        "{%0,%1,%2,%3}, {%4,%5,%6,%7}, {%8,%9}, {%0,%1,%2,%3};"
        : "+f"(c[0]), "+f"(c[1]), "+f"(c[2]), "+f"(c[3])
        : "r"(a[0]), "r"(a[1]), "r"(a[2]), "r"(a[3]), "r"(b[0]), "r"(b[1]));
}
__device__ __forceinline__ void mma_fp(float* c, const uint32_t* a, const uint32_t* b){
    asm volatile("mma.sync.aligned.m16n8k16.row.col.f32.f16.f16.f32 "
        "{%0,%1,%2,%3}, {%4,%5,%6,%7}, {%8,%9}, {%0,%1,%2,%3};"
        : "+f"(c[0]), "+f"(c[1]), "+f"(c[2]), "+f"(c[3])
        : "r"(a[0]), "r"(a[1]), "r"(a[2]), "r"(a[3]), "r"(b[0]), "r"(b[1]));
}
__device__ __forceinline__ void cpa16(uint32_t dst, const void* src){
    asm volatile("cp.async.cg.shared.global [%0], [%1], 16;" :: "r"(dst), "l"(src));
}
__device__ __forceinline__ void split_bf(float v, __nv_bfloat16& h, __nv_bfloat16& l){
    h = __float2bfloat16(v); l = __float2bfloat16(v - __bfloat162float(h));
}
__device__ __forceinline__ void split_h(float v, __half& h, __half& l){
    h = __float2half(v); l = __float2half(v - __half2float(h));
}

// ---------------- concat + bilinear (fp32 out) ----------------
__device__ __forceinline__ float bilerp(const float* __restrict__ s, int b, int Ci, int c, int S, int y, int x){
    float sc = (float)(S-1)/(float)(HW-1);
    float fy = y*sc, fx = x*sc;
    int y0 = (int)floorf(fy), x0 = (int)floorf(fx);
    int y1 = min(y0+1, S-1), x1 = min(x0+1, S-1);
    float wy = fy-y0, wx = fx-x0;
    const float* p = s + ((b*Ci+c)*S)*S;
    float v00=p[y0*S+x0], v01=p[y0*S+x1], v10=p[y1*S+x0], v11=p[y1*S+x1];
    return (v00*(1.f-wx)+v01*wx)*(1.f-wy) + (v10*(1.f-wx)+v11*wx)*wy;
}
__global__ void concat_kernel(const float* __restrict__ f1, const float* __restrict__ f2,
                              const float* __restrict__ f3, const float* __restrict__ f4){
    int idx = blockIdx.x*blockDim.x + threadIdx.x;
    if (idx >= M_TOT*C0) return;
    int c = idx % C0, m = idx / C0;
    int x = m%HW, y = (m/HW)%HW, b = m/(HW*HW);
    float v;
    if (c < 48)       v = f1[((b*48+c)*HW+y)*HW+x];
    else if (c < 144) v = bilerp(f2,b, 96,c-48, 48,y,x);
    else if (c < 336) v = bilerp(f3,b,192,c-144,24,y,x);
    else              v = bilerp(f4,b,384,c-336,12,y,x);
    g_feats[idx] = v;
}

// ---------------- F(4x4,3x3) weight transform: U = 256 * G g G^T ----------------
__global__ void wino_w(const float* __restrict__ w){
    int idx = blockIdx.x*blockDim.x + threadIdx.x;
    if (idx >= UCH) return;
    int ci = idx % C0, co = idx / C0;
    float g[3][3];
    #pragma unroll
    for (int r=0;r<3;r++)
        #pragma unroll
        for (int c=0;c<3;c++) g[r][c] = w[(co*C0+ci)*9 + r*3 + c];
    float T[6][3];
    #pragma unroll
    for (int c=0;c<3;c++){
        float g0=g[0][c], g1=g[1][c], g2=g[2][c];
        T[0][c] = 0.25f*g0;
        T[1][c] = (-g0-g1-g2)*(1.f/6.f);
        T[2][c] = (-g0+g1-g2)*(1.f/6.f);
        T[3][c] = g0*(1.f/24.f) + g1*(1.f/12.f) + g2*(1.f/6.f);
        T[4][c] = g0*(1.f/24.f) - g1*(1.f/12.f) + g2*(1.f/6.f);
        T[5][c] = g2;
    }
    #pragma unroll
    for (int i=0;i<6;i++){
        float t0=T[i][0], t1=T[i][1], t2=T[i][2];
        float U[6];
        U[0] = 0.25f*t0;
        U[1] = (-t0-t1-t2)*(1.f/6.f);
        U[2] = (-t0+t1-t2)*(1.f/6.f);
        U[3] = t0*(1.f/24.f) + t1*(1.f/12.f) + t2*(1.f/6.f);
        U[4] = t0*(1.f/24.f) - t1*(1.f/12.f) + t2*(1.f/6.f);
        U[5] = t2;
        #pragma unroll
        for (int j=0;j<6;j++){
            __half h,l; split_h(U[j]*256.f, h, l);
            long o = (long)(i*6+j)*UCH + (long)co*C0 + ci;   // [u][co][ci]
            g_Uh[o]=h; g_Ul[o]=l;
        }
    }
}

// ---------------- F(4x4,3x3) input transform: V = B^T d B ----------------
__global__ void wino_in(){
    int idx = blockIdx.x*blockDim.x + threadIdx.x;
    if (idx >= TCH4) return;
    int ci = idx % C0, t = idx / C0;
    int b = t/576, rem = t%576, ty = rem/24, tx = rem%24;
    int iy = 4*ty-1, ix = 4*tx-1;
    float T[6][6];
    #pragma unroll
    for (int j=0;j<6;j++){
        int x = ix+j;
        float d[6];
        #pragma unroll
        for (int k=0;k<6;k++){
            int y = iy+k;
            d[k] = (((unsigned)y<HW)&&((unsigned)x<HW)) ?
                g_feats[((long)((b*HW+y)*HW+x))*C0 + ci] : 0.f;
        }
        T[0][j] = 4.f*d[0] - 5.f*d[2] + d[4];
        T[1][j] = -4.f*d[1] - 4.f*d[2] + d[3] + d[4];
        T[2][j] =  4.f*d[1] - 4.f*d[2] - d[3] + d[4];
        T[3][j] = -2.f*d[1] - d[2] + 2.f*d[3] + d[4];
        T[4][j] =  2.f*d[1] - d[2] - 2.f*d[3] + d[4];
        T[5][j] =  4.f*d[1] - 5.f*d[3] + d[5];
    }
    #pragma unroll
    for (int i=0;i<6;i++){
        float t0=T[i][0], t1=T[i][1], t2=T[i][2], t3=T[i][3], t4=T[i][4], t5=T[i][5];
        float V[6];
        V[0] = 4.f*t0 - 5.f*t2 + t4;
        V[1] = -4.f*t1 - 4.f*t2 + t3 + t4;
        V[2] =  4.f*t1 - 4.f*t2 - t3 + t4;
        V[3] = -2.f*t1 - t2 + 2.f*t3 + t4;
        V[4] =  2.f*t1 - t2 - 2.f*t3 + t4;
        V[5] =  4.f*t1 - 5.f*t3 + t5;
        #pragma unroll
        for (int j=0;j<6;j++){
            __half h,l; split_h(V[j], h, l);
            long o = (long)(i*6+j)*TCH4 + (long)t*C0 + ci;   // [u][t][ci]
            g_Vh[o]=h; g_Vl[o]=l;
        }
    }
}

// ---------------- unified K=720 GEMM, 3-term split, 4-stage, 2 CTA/SM ----------------
// EPI 0: fp16: A=g_V*(plane z, M=1152), B=g_U*(plane z) -> g_M fp32
// EPI 1: bf16: A=g_c*,  B=g_w1* -> BN2+ReLU -> g_p1*
// EPI 2: bf16: A=g_p1*, B=g_w2* -> +pb2 -> g_p2
template<int EPI>
__global__ __launch_bounds__(THR,2) void gemm_u(const float* __restrict__ pb2){
    extern __shared__ __align__(128) char smem[];
    const uint32_t su = smem_u32(smem);
    const int tid = threadIdx.x, lane = tid&31, wid = tid>>5;
    const int wm = wid&3, wn = wid>>2;
    const int m0 = blockIdx.y*BM, n0 = blockIdx.x*BN;
    const int nIter = C0/BK;   // 45

    const char *pAh, *pAl, *pBh, *pBl;
    if (EPI==0){
        long zA = (long)blockIdx.z*TCH4, zB = (long)blockIdx.z*UCH;
        pAh = (const char*)(g_Vh + zA); pAl = (const char*)(g_Vl + zA);
        pBh = (const char*)(g_Uh + zB); pBl = (const char*)(g_Ul + zB);
    } else if (EPI==1){
        pAh = (const char*)g_ch;  pAl = (const char*)g_cl;
        pBh = (const char*)g_w1h; pBl = (const char*)g_w1l;
    } else {
        pAh = (const char*)g_p1h; pAl = (const char*)g_p1l;
        pBh = (const char*)g_w2h; pBl = (const char*)g_w2l;
    }

    bool valid[NSLOT], isA[NSLOT], plane[NSLOT];
    int dstv[NSLOT], srcb[NSLOT];
    #pragma unroll
    for (int p=0;p<NSLOT;p++){
        int i = tid + p*THR;
        valid[p] = (i < NCHUNK);
        isA[p]=false; plane[p]=false; dstv[p]=0; srcb[p]=0;
        if (!valid[p]) continue;
        if (i < 512){
            isA[p] = true;
            int pl = i>>8, j = i&255, r = j>>1, c = j&1;
            plane[p] = pl;
            dstv[p] = pl*A_PL + r*ROWB + c*16;
            srcb[p] = (m0+r)*(C0*2) + c*16;
        } else {
            int ib = i-512;
            int pl = (ib>=288), jb = ib - pl*288, r = jb>>1, c = jb&1;
            plane[p] = pl;
            dstv[p] = 2*A_PL + pl*B_PL + r*ROWB + c*16;
            srcb[p] = (n0+r)*(C0*2) + c*16;
        }
    }

    auto load_stage = [&](int it){
        uint32_t sb = su + (it & (NSTAGE-1))*STG;
        int addK = it*BK*2;
        #pragma unroll
        for (int p=0;p<NSLOT;p++){
            if (!valid[p]) continue;
            const char* base = isA[p] ? (plane[p]? pAl : pAh) : (plane[p]? pBl : pBh);
            cpa16(sb + dstv[p], base + srcb[p] + addK);
        }
        asm volatile("cp.async.commit_group;" ::: "memory");
    };

    float acc[2][9][4];
    #pragma unroll
    for (int a=0;a<2;a++)
        #pragma unroll
        for (int b=0;b<9;b++)
            #pragma unroll
            for (int c=0;c<4;c++) acc[a][b][c]=0.f;

    load_stage(0); load_stage(1); load_stage(2);

    for (int it=0; it<nIter; ++it){
        int rem = nIter-1-it;
        if (rem>=2)      asm volatile("cp.async.wait_group 2;" ::: "memory");
        else if (rem==1) asm volatile("cp.async.wait_group 1;" ::: "memory");
        else             asm volatile("cp.async.wait_group 0;" ::: "memory");
        __syncthreads();
        if (it+3 < nIter) load_stage(it+3);

        uint32_t sb = su + (it & (NSTAGE-1))*STG;
        uint32_t ah[2][4], al[2][4];
        #pragma unroll
        for (int mt=0;mt<2;mt++){
            uint32_t row = wm*32 + mt*16 + (lane&15);
            uint32_t ad = sb + row*ROWB + (lane>>4)*16;
            ldsm4(ah[mt], ad);
            ldsm4(al[mt], ad + A_PL);
        }
        #pragma unroll
        for (int np=0;np<5;np++){
            if (np<4){
                uint32_t n = wn*72 + np*16 + (lane>>4)*8 + (lane&7);
                uint32_t ad = sb + 2*A_PL + n*ROWB + ((lane>>3)&1)*16;
                uint32_t bh[4], bl[4];
                ldsm4(bh, ad);
                ldsm4(bl, ad + B_PL);
                #pragma unroll
                for (int h=0;h<2;h++){
                    int nt = np*2+h;
                    #pragma unroll
                    for (int mt=0;mt<2;mt++){
                        if (EPI==0){
                            mma_fp(acc[mt][nt], ah[mt], bh+2*h);
                            mma_fp(acc[mt][nt], ah[mt], bl+2*h);
                            mma_fp(acc[mt][nt], al[mt], bh+2*h);
                        } else {
                            mma_bf(acc[mt][nt], ah[mt], bh+2*h);
                            mma_bf(acc[mt][nt], ah[mt], bl+2*h);
                            mma_bf(acc[mt][nt], al[mt], bh+2*h);
                        }
                    }
                }
            } else {
                uint32_t n = wn*72 + 64 + (lane&7);
                uint32_t ad = sb + 2*A_PL + n*ROWB + ((lane>>3)&1)*16;
                uint32_t bh[2], bl[2];
                ldsm2(bh, ad);
                ldsm2(bl, ad + B_PL);
                #pragma unroll
                for (int mt=0;mt<2;mt++){
                    if (EPI==0){
                        mma_fp(acc[mt][8], ah[mt], bh);
                        mma_fp(acc[mt][8], ah[mt], bl);
                        mma_fp(acc[mt][8], al[mt], bh);
                    } else {
                        mma_bf(acc[mt][8], ah[mt], bh);
                        mma_bf(acc[mt][8], ah[mt], bl);
                        mma_bf(acc[mt][8], al[mt], bh);
                    }
                }
            }
        }
    }

    #pragma unroll
    for (int mt=0;mt<2;mt++){
        #pragma unroll
        for (int nt=0;nt<9;nt++){
            #pragma unroll
            for (int h=0;h<2;h++){
                int m = m0 + wm*32 + mt*16 + (lane>>2) + h*8;
                int n = n0 + wn*72 + nt*8 + (lane&3)*2;
                float v0 = acc[mt][nt][2*h], v1 = acc[mt][nt][2*h+1];
                if (EPI==0){
                    float2 o; o.x = v0; o.y = v1;
                    *(float2*)(g_M + (long)blockIdx.z*TCH4 + (long)m*C0 + n) = o;
                } else if (EPI==2){
                    float2 o; o.x = v0 + pb2[n]; o.y = v1 + pb2[n+1];
                    *(float2*)(g_p2 + (long)m*C0 + n) = o;
                } else {
                    float r0 = fmaxf(fmaf(v0, g_s2[n],   g_t2[n]),   0.f);
                    float r1 = fmaxf(fmaf(v1, g_s2[n+1], g_t2[n+1]), 0.f);
                    __nv_bfloat16 h0,l0,h1,l1;
                    split_bf(r0,h0,l0); split_bf(r1,h1,l1);
                    uint32_t ph = (uint32_t)__bfloat16_as_ushort(h0) | ((uint32_t)__bfloat16_as_ushort(h1)<<16);
                    uint32_t plv = (uint32_t)__bfloat16_as_ushort(l0) | ((uint32_t)__bfloat16_as_ushort(l1)<<16);
                    *(uint32_t*)(g_p1h + (long)m*C0 + n) = ph;
                    *(uint32_t*)(g_p1l + (long)m*C0 + n) = plv;
                }
            }
        }
    }
}

// ---------------- F(4x4) output transform + BN1 + ReLU + split ----------------
__global__ void wino_out(){
    int idx = blockIdx.x*blockDim.x + threadIdx.x;
    if (idx >= TCH4) return;
    int co = idx % C0, t = idx / C0;
    float m[36];
    #pragma unroll
    for (int u=0;u<36;u++) m[u] = g_M[(long)u*TCH4 + (long)t*C0 + co] * (1.f/256.f);
    float Z[4][6];
    #pragma unroll
    for (int j=0;j<6;j++){
        float m0=m[0*6+j], m1=m[1*6+j], m2=m[2*6+j], m3=m[3*6+j], m4=m[4*6+j], m5=m[5*6+j];
        Z[0][j] = m0+m1+m2+m3+m4;
        Z[1][j] = m1-m2+2.f*(m3-m4);
        Z[2][j] = m1+m2+4.f*(m3+m4);
        Z[3][j] = m1-m2+8.f*(m3-m4)+m5;
    }
    int b = t/576, rem = t%576, ty = rem/24, tx = rem%24;
    float s = g_s1[co], tt = g_t1[co];
    #pragma unroll
    for (int i=0;i<4;i++){
        float z0=Z[i][0], z1=Z[i][1], z2=Z[i][2], z3=Z[i][3], z4=Z[i][4], z5=Z[i][5];
        float Y[4];
        Y[0] = z0+z1+z2+z3+z4;
        Y[1] = z1-z2+2.f*(z3-z4);
        Y[2] = z1+z2+4.f*(z3+z4);
        Y[3] = z1-z2+8.f*(z3-z4)+z5;
        #pragma unroll
        for (int j=0;j<4;j++){
            float v = fmaxf(fmaf(Y[j], s, tt), 0.f);
            __nv_bfloat16 h,l; split_bf(v,h,l);
            long o = ((long)((b*HW + 4*ty+i)*HW + 4*tx+j))*C0 + co;
            g_ch[o]=h; g_cl[o]=l;
        }
    }
}

// ---------------- prep ----------------
__global__ void prep_w1x1(const float* __restrict__ w1, const float* __restrict__ w2){
    int idx = blockIdx.x*blockDim.x + threadIdx.x;
    if (idx >= UCH) return;
    int cout = idx / C0, cin = idx % C0;
    __nv_bfloat16 h,l;
    split_bf(w1[cout*C0+cin],h,l); g_w1h[idx]=h; g_w1l[idx]=l;
    split_bf(w2[cout*C0+cin],h,l); g_w2h[idx]=h; g_w2l[idx]=l;
}
__global__ void prep_bn(const float* __restrict__ cb, const float* __restrict__ g1, const float* __restrict__ b1,
                        const float* __restrict__ rm1, const float* __restrict__ rv1, const float* __restrict__ pb1,
                        const float* __restrict__ g2, const float* __restrict__ b2,
                        const float* __restrict__ rm2, const float* __restrict__ rv2){
    int n = blockIdx.x*blockDim.x + threadIdx.x;
    if (n >= C0) return;
    float s1 = g1[n]*rsqrtf(rv1[n]+1e-5f);
    g_s1[n]=s1; g_t1[n]=(cb[n]-rm1[n])*s1+b1[n];
    float s2 = g2[n]*rsqrtf(rv2[n]+1e-5f);
    g_s2[n]=s2; g_t2[n]=(pb1[n]-rm2[n])*s2+b2[n];
}
__global__ void prep_proto(const float* __restrict__ pr){
    int w = blockIdx.x, lane = threadIdx.x & 31;
    float ss = 0.f;
    for (int i=lane;i<C0;i+=32){ float v=pr[w*C0+i]; ss+=v*v; }
    #pragma unroll
    for (int o=16;o;o>>=1) ss += __shfl_xor_sync(0xffffffffu, ss, o);
    float inv = 1.f/fmaxf(sqrtf(ss),1e-12f);
    for (int i=lane;i<C0;i+=32) g_proton[w*C0+i] = pr[w*C0+i]*inv;
}

// ---------------- head ----------------
__global__ void head_kernel(const float* __restrict__ lng, const float* __restrict__ lnb,
                            const float* __restrict__ lmg, const float* __restrict__ lmb,
                            float* __restrict__ out){
    int warp = (blockIdx.x*blockDim.x + threadIdx.x)>>5;
    int lane = threadIdx.x & 31;
    if (warp >= M_TOT) return;
    const float* row = g_p2 + (long)warp*C0;
    float v[23]; float s=0.f, ss=0.f;
    #pragma unroll
    for (int i=0;i<23;i++){
        int idx = lane + i*32;
        float x = (idx<C0)? row[idx] : 0.f;
        v[i]=x; s+=x; ss+=x*x;
    }
    #pragma unroll
    for (int o=16;o;o>>=1){ s+=__shfl_xor_sync(0xffffffffu,s,o); ss+=__shfl_xor_sync(0xffffffffu,ss,o); }
    float mu = s/(float)C0;
    float rstd = rsqrtf(ss/(float)C0 - mu*mu + 1e-5f);
    float q = 0.f;
    #pragma unroll
    for (int i=0;i<23;i++){
        int idx = lane + i*32;
        float x = (idx<C0)? (v[i]-mu)*rstd*lng[idx]+lnb[idx] : 0.f;
        v[i]=x; q+=x*x;
    }
    #pragma unroll
    for (int o=16;o;o>>=1) q+=__shfl_xor_sync(0xffffffffu,q,o);
    float inv = 1.f/fmaxf(sqrtf(q),1e-12f);
    float mx0=-1e30f, mx1=-1e30f;
    for (int p=0;p<NPROTO;p++){
        float d=0.f;
        const float* pp = g_proton + p*C0;
        #pragma unroll
        for (int i=0;i<23;i++){
            int idx = lane + i*32;
            if (idx<C0) d += v[i]*pp[idx];
        }
        #pragma unroll
        for (int o=16;o;o>>=1) d+=__shfl_xor_sync(0xffffffffu,d,o);
        d *= inv;
        if (p<10) mx0=fmaxf(mx0,d); else mx1=fmaxf(mx1,d);
    }
    if (lane==0){
        float mu2 = 0.5f*(mx0+mx1);
        float d0 = mx0-mu2, d1 = mx1-mu2;
        float r2 = rsqrtf(0.5f*(d0*d0+d1*d1)+1e-5f);
        int m = warp;
        int x = m%HW, y = (m/HW)%HW, b = m/(HW*HW);
        out[((b*2+0)*HW+y)*HW+x] = d0*r2*lmg[0]+lmb[0];
        out[((b*2+1)*HW+y)*HW+x] = d1*r2*lmg[1]+lmb[1];
    }
}

extern "C" void kernel_launch(void* const* d_in, const int* in_sizes, int n_in,
                              void* d_out, int out_size){
    const float* feat1=(const float*)d_in[0];  const float* feat2=(const float*)d_in[1];
    const float* feat3=(const float*)d_in[2];  const float* feat4=(const float*)d_in[3];
    const float* cls_w=(const float*)d_in[4];  const float* cls_b=(const float*)d_in[5];
    const float* cbn_g=(const float*)d_in[6];  const float* cbn_b=(const float*)d_in[7];
    const float* cbn_rm=(const float*)d_in[8]; const float* cbn_rv=(const float*)d_in[9];
    const float* pw1=(const float*)d_in[10];   const float* pb1=(const float*)d_in[11];
    const float* pbn_g=(const float*)d_in[12]; const float* pbn_b=(const float*)d_in[13];
    const float* pbn_rm=(const float*)d_in[14];const float* pbn_rv=(const float*)d_in[15];
    const float* pw2=(const float*)d_in[16];   const float* pb2=(const float*)d_in[17];
    const float* lnf_g=(const float*)d_in[18]; const float* lnf_b=(const float*)d_in[19];
    const float* lnm_g=(const float*)d_in[20]; const float* lnm_b=(const float*)d_in[21];
    const float* protos=(const float*)d_in[22];
    float* out = (float*)d_out;

    static int smem_set = 0;
    if (!smem_set){
        cudaFuncSetAttribute(gemm_u<0>, cudaFuncAttributeMaxDynamicSharedMemorySize, SMEM_DYN);
        cudaFuncSetAttribute(gemm_u<1>, cudaFuncAttributeMaxDynamicSharedMemorySize, SMEM_DYN);
        cudaFuncSetAttribute(gemm_u<2>, cudaFuncAttributeMaxDynamicSharedMemorySize, SMEM_DYN);
        smem_set = 1;
    }

    concat_kernel<<<(M_TOT*C0+255)/256, 256>>>(feat1, feat2, feat3, feat4);
    wino_w<<<(UCH+255)/256, 256>>>(cls_w);
    wino_in<<<(TCH4+255)/256, 256>>>();
    dim3 gw(5, NT4/BM, 36);   // (5,9,36) = 1620 CTAs
    gemm_u<0><<<gw, THR, SMEM_DYN>>>(nullptr);   // 4th launch: profiled
    prep_bn<<<3, 256>>>(cls_b, cbn_g, cbn_b, cbn_rm, cbn_rv, pb1, pbn_g, pbn_b, pbn_rm, pbn_rv);
    wino_out<<<(TCH4+255)/256, 256>>>();
    prep_w1x1<<<(UCH+255)/256, 256>>>(pw1, pw2);
    dim3 g1(5, M_TOT/BM, 1);    // (5,144)
    gemm_u<1><<<g1, THR, SMEM_DYN>>>(nullptr);
    gemm_u<2><<<g1, THR, SMEM_DYN>>>(pb2);
    prep_proto<<<NPROTO, 32>>>(protos);
    head_kernel<<<(M_TOT*32+255)/256, 256>>>(lnf_g, lnf_b, lnm_g, lnm_b, out);
    (void)in_sizes; (void)n_in; (void)out_size;
}

// round 15
// speedup vs baseline: 2.3249x; 1.0545x over previous
#include <cuda_runtime.h>
#include <cuda_bf16.h>
#include <cuda_fp16.h>
#include <math.h>
#include <stdint.h>

#define HW 96
#define C0 720
#define M_TOT 18432
#define NPROTO 20
#define NT6 512                      // F(6x6) tiles: 2*16*16
#define TCH6 (NT6*C0)                // 368640, one V/M plane
#define UCH (C0*C0)                  // 518400, one U plane
#define USC 512.f
#define BM 128
#define BN 144
#define BK 16
#define ROWB 48
#define A_PL (128*ROWB)
#define B_PL (144*ROWB)
#define STG (2*A_PL + 2*B_PL)        // 26112
#define NSTAGE 4
#define SMEM_DYN (NSTAGE*STG)        // 104448 -> 2 CTA/SM
#define NCHUNK 1088
#define THR 256
#define NSLOT 5

__device__ float g_feats[M_TOT*C0];
__device__ __half g_Vh[64L*TCH6], g_Vl[64L*TCH6];
__device__ __half g_Uh[64L*UCH], g_Ul[64L*UCH];
__device__ float g_M[64L*TCH6];
__device__ __nv_bfloat16 g_w1h[UCH], g_w1l[UCH];
__device__ __nv_bfloat16 g_w2h[UCH], g_w2l[UCH];
__device__ __nv_bfloat16 g_ch[M_TOT*C0], g_cl[M_TOT*C0];
__device__ __nv_bfloat16 g_p1h[M_TOT*C0], g_p1l[M_TOT*C0];
__device__ float g_p2[M_TOT*C0];
__device__ float g_s1[C0], g_t1[C0], g_s2[C0], g_t2[C0];
__device__ float g_proton[NPROTO*C0];

__device__ __forceinline__ uint32_t smem_u32(const void* p){
    uint32_t a;
    asm("{ .reg .u64 t; cvta.to.shared.u64 t, %1; cvt.u32.u64 %0, t; }" : "=r"(a) : "l"(p));
    return a;
}
__device__ __forceinline__ void ldsm4(uint32_t* r, uint32_t a){
    asm volatile("ldmatrix.sync.aligned.m8n8.x4.shared.b16 {%0,%1,%2,%3}, [%4];"
        : "=r"(r[0]), "=r"(r[1]), "=r"(r[2]), "=r"(r[3]) : "r"(a));
}
__device__ __forceinline__ void ldsm2(uint32_t* r, uint32_t a){
    asm volatile("ldmatrix.sync.aligned.m8n8.x2.shared.b16 {%0,%1}, [%2];"
        : "=r"(r[0]), "=r"(r[1]) : "r"(a));
}
__device__ __forceinline__ void mma_bf(float* c, const uint32_t* a, const uint32_t* b){
    asm volatile("mma.sync.aligned.m16n8k16.row.col.f32.bf16.bf16.f32 "
        "{%0,%1,%2,%3}, {%4,%5,%6,%7}, {%8,%9}, {%0,%1,%2,%3};"
        : "+f"(c[0]), "+f"(c[1]), "+f"(c[2]), "+f"(c[3])
        : "r"(a[0]), "r"(a[1]), "r"(a[2]), "r"(a[3]), "r"(b[0]), "r"(b[1]));
}
__device__ __forceinline__ void mma_fp(float* c, const uint32_t* a, const uint32_t* b){
    asm volatile("mma.sync.aligned.m16n8k16.row.col.f32.f16.f16.f32 "
        "{%0,%1,%2,%3}, {%4,%5,%6,%7}, {%8,%9}, {%0,%1,%2,%3};"
        : "+f"(c[0]), "+f"(c[1]), "+f"(c[2]), "+f"(c[3])
        : "r"(a[0]), "r"(a[1]), "r"(a[2]), "r"(a[3]), "r"(b[0]), "r"(b[1]));
}
__device__ __forceinline__ void cpa16(uint32_t dst, const void* src){
    asm volatile("cp.async.cg.shared.global [%0], [%1], 16;" :: "r"(dst), "l"(src));
}
__device__ __forceinline__ void split_bf(float v, __nv_bfloat16& h, __nv_bfloat16& l){
    h = __float2bfloat16(v); l = __float2bfloat16(v - __bfloat162float(h));
}
__device__ __forceinline__ void split_h(float v, __half& h, __half& l){
    h = __float2half(v); l = __float2half(v - __half2float(h));
}

// ---------------- concat + bilinear (fp32 out) ----------------
__device__ __forceinline__ float bilerp(const float* __restrict__ s, int b, int Ci, int c, int S, int y, int x){
    float sc = (float)(S-1)/(float)(HW-1);
    float fy = y*sc, fx = x*sc;
    int y0 = (int)floorf(fy), x0 = (int)floorf(fx);
    int y1 = min(y0+1, S-1), x1 = min(x0+1, S-1);
    float wy = fy-y0, wx = fx-x0;
    const float* p = s + ((b*Ci+c)*S)*S;
    float v00=p[y0*S+x0], v01=p[y0*S+x1], v10=p[y1*S+x0], v11=p[y1*S+x1];
    return (v00*(1.f-wx)+v01*wx)*(1.f-wy) + (v10*(1.f-wx)+v11*wx)*wy;
}
__global__ void concat_kernel(const float* __restrict__ f1, const float* __restrict__ f2,
                              const float* __restrict__ f3, const float* __restrict__ f4){
    int idx = blockIdx.x*blockDim.x + threadIdx.x;
    if (idx >= M_TOT*C0) return;
    int c = idx % C0, m = idx / C0;
    int x = m%HW, y = (m/HW)%HW, b = m/(HW*HW);
    float v;
    if (c < 48)       v = f1[((b*48+c)*HW+y)*HW+x];
    else if (c < 144) v = bilerp(f2,b, 96,c-48, 48,y,x);
    else if (c < 336) v = bilerp(f3,b,192,c-144,24,y,x);
    else              v = bilerp(f4,b,384,c-336,12,y,x);
    g_feats[idx] = v;
}

// ---------------- F(6x6,3x3) weight transform: U = USC * G g G^T ----------------
__global__ void wino_w(const float* __restrict__ w){
    int idx = blockIdx.x*blockDim.x + threadIdx.x;
    if (idx >= UCH) return;
    int ci = idx % C0, co = idx / C0;
    float g[3][3];
    #pragma unroll
    for (int r=0;r<3;r++)
        #pragma unroll
        for (int c=0;c<3;c++) g[r][c] = w[(co*C0+ci)*9 + r*3 + c];
    float T[8][3];
    #pragma unroll
    for (int c=0;c<3;c++){
        float g0=g[0][c], g1=g[1][c], g2=g[2][c];
        T[0][c] = g0;
        T[1][c] = (-2.f/9.f)*(g0+g1+g2);
        T[2][c] = (-2.f/9.f)*(g0-g1+g2);
        T[3][c] = g0*(1.f/90.f) + g1*(1.f/45.f) + g2*(2.f/45.f);
        T[4][c] = g0*(1.f/90.f) - g1*(1.f/45.f) + g2*(2.f/45.f);
        T[5][c] = g0*(32.f/45.f) + g1*(16.f/45.f) + g2*(8.f/45.f);
        T[6][c] = g0*(32.f/45.f) - g1*(16.f/45.f) + g2*(8.f/45.f);
        T[7][c] = g2;
    }
    #pragma unroll
    for (int i=0;i<8;i++){
        float t0=T[i][0], t1=T[i][1], t2=T[i][2];
        float U[8];
        U[0] = t0;
        U[1] = (-2.f/9.f)*(t0+t1+t2);
        U[2] = (-2.f/9.f)*(t0-t1+t2);
        U[3] = t0*(1.f/90.f) + t1*(1.f/45.f) + t2*(2.f/45.f);
        U[4] = t0*(1.f/90.f) - t1*(1.f/45.f) + t2*(2.f/45.f);
        U[5] = t0*(32.f/45.f) + t1*(16.f/45.f) + t2*(8.f/45.f);
        U[6] = t0*(32.f/45.f) - t1*(16.f/45.f) + t2*(8.f/45.f);
        U[7] = t2;
        #pragma unroll
        for (int j=0;j<8;j++){
            __half h,l; split_h(U[j]*USC, h, l);
            long o = (long)(i*8+j)*UCH + (long)co*C0 + ci;   // [u][co][ci]
            g_Uh[o]=h; g_Ul[o]=l;
        }
    }
}

// ---------------- F(6x6,3x3) input transform: V = B^T d B ----------------
__global__ void wino_in(){
    int idx = blockIdx.x*blockDim.x + threadIdx.x;
    if (idx >= TCH6) return;
    int ci = idx % C0, t = idx / C0;
    int b = t/256, rem = t%256, ty = rem/16, tx = rem%16;
    int iy = 6*ty-1, ix = 6*tx-1;
    float T[8][8];
    #pragma unroll
    for (int j=0;j<8;j++){
        int x = ix+j;
        float d[8];
        #pragma unroll
        for (int k=0;k<8;k++){
            int y = iy+k;
            d[k] = (((unsigned)y<HW)&&((unsigned)x<HW)) ?
                g_feats[((long)((b*HW+y)*HW+x))*C0 + ci] : 0.f;
        }
        T[0][j] = d[0] - 5.25f*d[2] + 5.25f*d[4] - d[6];
        T[1][j] = d[1] + d[2] - 4.25f*(d[3]+d[4]) + d[5] + d[6];
        T[2][j] = -d[1] + d[2] + 4.25f*(d[3]-d[4]) - d[5] + d[6];
        T[3][j] = 0.5f*d[1] + 0.25f*d[2] - 2.5f*d[3] - 1.25f*d[4] + 2.f*d[5] + d[6];
        T[4][j] = -0.5f*d[1] + 0.25f*d[2] + 2.5f*d[3] - 1.25f*d[4] - 2.f*d[5] + d[6];
        T[5][j] = 2.f*d[1] + 4.f*d[2] - 2.5f*d[3] - 5.f*d[4] + 0.5f*d[5] + d[6];
        T[6][j] = -2.f*d[1] + 4.f*d[2] + 2.5f*d[3] - 5.f*d[4] - 0.5f*d[5] + d[6];
        T[7][j] = -d[1] + 5.25f*d[3] - 5.25f*d[5] + d[7];
    }
    #pragma unroll
    for (int i=0;i<8;i++){
        float* r = T[i];
        float V[8];
        V[0] = r[0] - 5.25f*r[2] + 5.25f*r[4] - r[6];
        V[1] = r[1] + r[2] - 4.25f*(r[3]+r[4]) + r[5] + r[6];
        V[2] = -r[1] + r[2] + 4.25f*(r[3]-r[4]) - r[5] + r[6];
        V[3] = 0.5f*r[1] + 0.25f*r[2] - 2.5f*r[3] - 1.25f*r[4] + 2.f*r[5] + r[6];
        V[4] = -0.5f*r[1] + 0.25f*r[2] + 2.5f*r[3] - 1.25f*r[4] - 2.f*r[5] + r[6];
        V[5] = 2.f*r[1] + 4.f*r[2] - 2.5f*r[3] - 5.f*r[4] + 0.5f*r[5] + r[6];
        V[6] = -2.f*r[1] + 4.f*r[2] + 2.5f*r[3] - 5.f*r[4] - 0.5f*r[5] + r[6];
        V[7] = -r[1] + 5.25f*r[3] - 5.25f*r[5] + r[7];
        #pragma unroll
        for (int j=0;j<8;j++){
            __half h,l; split_h(V[j], h, l);
            long o = (long)(i*8+j)*TCH6 + (long)t*C0 + ci;   // [u][t][ci]
            g_Vh[o]=h; g_Vl[o]=l;
        }
    }
}

// ---------------- unified K=720 GEMM, 3-term split, 4-stage, 2 CTA/SM ----------------
// EPI 0: fp16: A=g_V*(plane z, M=512), B=g_U*(plane z) -> g_M fp32
// EPI 1: bf16: A=g_c*,  B=g_w1* -> BN2+ReLU -> g_p1*
// EPI 2: bf16: A=g_p1*, B=g_w2* -> +pb2 -> g_p2
template<int EPI>
__global__ __launch_bounds__(THR,2) void gemm_u(const float* __restrict__ pb2){
    extern __shared__ __align__(128) char smem[];
    const uint32_t su = smem_u32(smem);
    const int tid = threadIdx.x, lane = tid&31, wid = tid>>5;
    const int wm = wid&3, wn = wid>>2;
    const int m0 = blockIdx.y*BM, n0 = blockIdx.x*BN;
    const int nIter = C0/BK;   // 45

    const char *pAh, *pAl, *pBh, *pBl;
    if (EPI==0){
        long zA = (long)blockIdx.z*TCH6, zB = (long)blockIdx.z*UCH;
        pAh = (const char*)(g_Vh + zA); pAl = (const char*)(g_Vl + zA);
        pBh = (const char*)(g_Uh + zB); pBl = (const char*)(g_Ul + zB);
    } else if (EPI==1){
        pAh = (const char*)g_ch;  pAl = (const char*)g_cl;
        pBh = (const char*)g_w1h; pBl = (const char*)g_w1l;
    } else {
        pAh = (const char*)g_p1h; pAl = (const char*)g_p1l;
        pBh = (const char*)g_w2h; pBl = (const char*)g_w2l;
    }

    bool valid[NSLOT], isA[NSLOT], plane[NSLOT];
    int dstv[NSLOT], srcb[NSLOT];
    #pragma unroll
    for (int p=0;p<NSLOT;p++){
        int i = tid + p*THR;
        valid[p] = (i < NCHUNK);
        isA[p]=false; plane[p]=false; dstv[p]=0; srcb[p]=0;
        if (!valid[p]) continue;
        if (i < 512){
            isA[p] = true;
            int pl = i>>8, j = i&255, r = j>>1, c = j&1;
            plane[p] = pl;
            dstv[p] = pl*A_PL + r*ROWB + c*16;
            srcb[p] = (m0+r)*(C0*2) + c*16;
        } else {
            int ib = i-512;
            int pl = (ib>=288), jb = ib - pl*288, r = jb>>1, c = jb&1;
            plane[p] = pl;
            dstv[p] = 2*A_PL + pl*B_PL + r*ROWB + c*16;
            srcb[p] = (n0+r)*(C0*2) + c*16;
        }
    }

    auto load_stage = [&](int it){
        uint32_t sb = su + (it & (NSTAGE-1))*STG;
        int addK = it*BK*2;
        #pragma unroll
        for (int p=0;p<NSLOT;p++){
            if (!valid[p]) continue;
            const char* base = isA[p] ? (plane[p]? pAl : pAh) : (plane[p]? pBl : pBh);
            cpa16(sb + dstv[p], base + srcb[p] + addK);
        }
        asm volatile("cp.async.commit_group;" ::: "memory");
    };

    float acc[2][9][4];
    #pragma unroll
    for (int a=0;a<2;a++)
        #pragma unroll
        for (int b=0;b<9;b++)
            #pragma unroll
            for (int c=0;c<4;c++) acc[a][b][c]=0.f;

    load_stage(0); load_stage(1); load_stage(2);

    for (int it=0; it<nIter; ++it){
        int rem = nIter-1-it;
        if (rem>=2)      asm volatile("cp.async.wait_group 2;" ::: "memory");
        else if (rem==1) asm volatile("cp.async.wait_group 1;" ::: "memory");
        else             asm volatile("cp.async.wait_group 0;" ::: "memory");
        __syncthreads();
        if (it+3 < nIter) load_stage(it+3);

        uint32_t sb = su + (it & (NSTAGE-1))*STG;
        uint32_t ah[2][4], al[2][4];
        #pragma unroll
        for (int mt=0;mt<2;mt++){
            uint32_t row = wm*32 + mt*16 + (lane&15);
            uint32_t ad = sb + row*ROWB + (lane>>4)*16;
            ldsm4(ah[mt], ad);
            ldsm4(al[mt], ad + A_PL);
        }
        #pragma unroll
        for (int np=0;np<5;np++){
            if (np<4){
                uint32_t n = wn*72 + np*16 + (lane>>4)*8 + (lane&7);
                uint32_t ad = sb + 2*A_PL + n*ROWB + ((lane>>3)&1)*16;
                uint32_t bh[4], bl[4];
                ldsm4(bh, ad);
                ldsm4(bl, ad + B_PL);
                #pragma unroll
                for (int h=0;h<2;h++){
                    int nt = np*2+h;
                    #pragma unroll
                    for (int mt=0;mt<2;mt++){
                        if (EPI==0){
                            mma_fp(acc[mt][nt], ah[mt], bh+2*h);
                            mma_fp(acc[mt][nt], ah[mt], bl+2*h);
                            mma_fp(acc[mt][nt], al[mt], bh+2*h);
                        } else {
                            mma_bf(acc[mt][nt], ah[mt], bh+2*h);
                            mma_bf(acc[mt][nt], ah[mt], bl+2*h);
                            mma_bf(acc[mt][nt], al[mt], bh+2*h);
                        }
                    }
                }
            } else {
                uint32_t n = wn*72 + 64 + (lane&7);
                uint32_t ad = sb + 2*A_PL + n*ROWB + ((lane>>3)&1)*16;
                uint32_t bh[2], bl[2];
                ldsm2(bh, ad);
                ldsm2(bl, ad + B_PL);
                #pragma unroll
                for (int mt=0;mt<2;mt++){
                    if (EPI==0){
                        mma_fp(acc[mt][8], ah[mt], bh);
                        mma_fp(acc[mt][8], ah[mt], bl);
                        mma_fp(acc[mt][8], al[mt], bh);
                    } else {
                        mma_bf(acc[mt][8], ah[mt], bh);
                        mma_bf(acc[mt][8], ah[mt], bl);
                        mma_bf(acc[mt][8], al[mt], bh);
                    }
                }
            }
        }
    }

    #pragma unroll
    for (int mt=0;mt<2;mt++){
        #pragma unroll
        for (int nt=0;nt<9;nt++){
            #pragma unroll
            for (int h=0;h<2;h++){
                int m = m0 + wm*32 + mt*16 + (lane>>2) + h*8;
                int n = n0 + wn*72 + nt*8 + (lane&3)*2;
                float v0 = acc[mt][nt][2*h], v1 = acc[mt][nt][2*h+1];
                if (EPI==0){
                    float2 o; o.x = v0; o.y = v1;
                    *(float2*)(g_M + (long)blockIdx.z*TCH6 + (long)m*C0 + n) = o;
                } else if (EPI==2){
                    float2 o; o.x = v0 + pb2[n]; o.y = v1 + pb2[n+1];
                    *(float2*)(g_p2 + (long)m*C0 + n) = o;
                } else {
                    float r0 = fmaxf(fmaf(v0, g_s2[n],   g_t2[n]),   0.f);
                    float r1 = fmaxf(fmaf(v1, g_s2[n+1], g_t2[n+1]), 0.f);
                    __nv_bfloat16 h0,l0,h1,l1;
                    split_bf(r0,h0,l0); split_bf(r1,h1,l1);
                    uint32_t ph = (uint32_t)__bfloat16_as_ushort(h0) | ((uint32_t)__bfloat16_as_ushort(h1)<<16);
                    uint32_t plv = (uint32_t)__bfloat16_as_ushort(l0) | ((uint32_t)__bfloat16_as_ushort(l1)<<16);
                    *(uint32_t*)(g_p1h + (long)m*C0 + n) = ph;
                    *(uint32_t*)(g_p1l + (long)m*C0 + n) = plv;
                }
            }
        }
    }
}

// ---------------- F(6x6) output transform + BN1 + ReLU + split ----------------
__global__ void wino_out(){
    int idx = blockIdx.x*blockDim.x + threadIdx.x;
    if (idx >= TCH6) return;
    int co = idx % C0, t = idx / C0;
    float Z[6][8];
    // first transform along rows of m while reading column-by-column
    #pragma unroll
    for (int j=0;j<8;j++){
        float m[8];
        #pragma unroll
        for (int k=0;k<8;k++)
            m[k] = g_M[(long)(k*8+j)*TCH6 + (long)t*C0 + co] * (1.f/USC);
        float a = m[1]+m[2], s = m[1]-m[2];
        float b4 = m[3]+m[4], s4 = m[3]-m[4];
        float c5 = m[5]+m[6], s5 = m[5]-m[6];
        Z[0][j] = m[0] + a + b4 + c5;
        Z[1][j] = s + 2.f*s4 + 0.5f*s5;
        Z[2][j] = a + 4.f*b4 + 0.25f*c5;
        Z[3][j] = s + 8.f*s4 + 0.125f*s5;
        Z[4][j] = a + 16.f*b4 + 0.0625f*c5;
        Z[5][j] = s + 32.f*s4 + 0.03125f*s5 + m[7];
    }
    int b = t/256, rem = t%256, ty = rem/16, tx = rem%16;
    float sc = g_s1[co], tt = g_t1[co];
    #pragma unroll
    for (int i=0;i<6;i++){
        float* z = Z[i];
        float a = z[1]+z[2], s = z[1]-z[2];
        float b4 = z[3]+z[4], s4 = z[3]-z[4];
        float c5 = z[5]+z[6], s5 = z[5]-z[6];
        float Y[6];
        Y[0] = z[0] + a + b4 + c5;
        Y[1] = s + 2.f*s4 + 0.5f*s5;
        Y[2] = a + 4.f*b4 + 0.25f*c5;
        Y[3] = s + 8.f*s4 + 0.125f*s5;
        Y[4] = a + 16.f*b4 + 0.0625f*c5;
        Y[5] = s + 32.f*s4 + 0.03125f*s5 + z[7];
        #pragma unroll
        for (int j=0;j<6;j++){
            float v = fmaxf(fmaf(Y[j], sc, tt), 0.f);
            __nv_bfloat16 h,l; split_bf(v,h,l);
            long o = ((long)((b*HW + 6*ty+i)*HW + 6*tx+j))*C0 + co;
            g_ch[o]=h; g_cl[o]=l;
        }
    }
}

// ---------------- prep ----------------
__global__ void prep_w1x1(const float* __restrict__ w1, const float* __restrict__ w2){
    int idx = blockIdx.x*blockDim.x + threadIdx.x;
    if (idx >= UCH) return;
    int cout = idx / C0, cin = idx % C0;
    __nv_bfloat16 h,l;
    split_bf(w1[cout*C0+cin],h,l); g_w1h[idx]=h; g_w1l[idx]=l;
    split_bf(w2[cout*C0+cin],h,l); g_w2h[idx]=h; g_w2l[idx]=l;
}
__global__ void prep_bn(const float* __restrict__ cb, const float* __restrict__ g1, const float* __restrict__ b1,
                        const float* __restrict__ rm1, const float* __restrict__ rv1, const float* __restrict__ pb1,
                        const float* __restrict__ g2, const float* __restrict__ b2,
                        const float* __restrict__ rm2, const float* __restrict__ rv2){
    int n = blockIdx.x*blockDim.x + threadIdx.x;
    if (n >= C0) return;
    float s1 = g1[n]*rsqrtf(rv1[n]+1e-5f);
    g_s1[n]=s1; g_t1[n]=(cb[n]-rm1[n])*s1+b1[n];
    float s2 = g2[n]*rsqrtf(rv2[n]+1e-5f);
    g_s2[n]=s2; g_t2[n]=(pb1[n]-rm2[n])*s2+b2[n];
}
__global__ void prep_proto(const float* __restrict__ pr){
    int w = blockIdx.x, lane = threadIdx.x & 31;
    float ss = 0.f;
    for (int i=lane;i<C0;i+=32){ float v=pr[w*C0+i]; ss+=v*v; }
    #pragma unroll
    for (int o=16;o;o>>=1) ss += __shfl_xor_sync(0xffffffffu, ss, o);
    float inv = 1.f/fmaxf(sqrtf(ss),1e-12f);
    for (int i=lane;i<C0;i+=32) g_proton[w*C0+i] = pr[w*C0+i]*inv;
}

// ---------------- head ----------------
__global__ void head_kernel(const float* __restrict__ lng, const float* __restrict__ lnb,
                            const float* __restrict__ lmg, const float* __restrict__ lmb,
                            float* __restrict__ out){
    int warp = (blockIdx.x*blockDim.x + threadIdx.x)>>5;
    int lane = threadIdx.x & 31;
    if (warp >= M_TOT) return;
    const float* row = g_p2 + (long)warp*C0;
    float v[23]; float s=0.f, ss=0.f;
    #pragma unroll
    for (int i=0;i<23;i++){
        int idx = lane + i*32;
        float x = (idx<C0)? row[idx] : 0.f;
        v[i]=x; s+=x; ss+=x*x;
    }
    #pragma unroll
    for (int o=16;o;o>>=1){ s+=__shfl_xor_sync(0xffffffffu,s,o); ss+=__shfl_xor_sync(0xffffffffu,ss,o); }
    float mu = s/(float)C0;
    float rstd = rsqrtf(ss/(float)C0 - mu*mu + 1e-5f);
    float q = 0.f;
    #pragma unroll
    for (int i=0;i<23;i++){
        int idx = lane + i*32;
        float x = (idx<C0)? (v[i]-mu)*rstd*lng[idx]+lnb[idx] : 0.f;
        v[i]=x; q+=x*x;
    }
    #pragma unroll
    for (int o=16;o;o>>=1) q+=__shfl_xor_sync(0xffffffffu,q,o);
    float inv = 1.f/fmaxf(sqrtf(q),1e-12f);
    float mx0=-1e30f, mx1=-1e30f;
    for (int p=0;p<NPROTO;p++){
        float d=0.f;
        const float* pp = g_proton + p*C0;
        #pragma unroll
        for (int i=0;i<23;i++){
            int idx = lane + i*32;
            if (idx<C0) d += v[i]*pp[idx];
        }
        #pragma unroll
        for (int o=16;o;o>>=1) d+=__shfl_xor_sync(0xffffffffu,d,o);
        d *= inv;
        if (p<10) mx0=fmaxf(mx0,d); else mx1=fmaxf(mx1,d);
    }
    if (lane==0){
        float mu2 = 0.5f*(mx0+mx1);
        float d0 = mx0-mu2, d1 = mx1-mu2;
        float r2 = rsqrtf(0.5f*(d0*d0+d1*d1)+1e-5f);
        int m = warp;
        int x = m%HW, y = (m/HW)%HW, b = m/(HW*HW);
        out[((b*2+0)*HW+y)*HW+x] = d0*r2*lmg[0]+lmb[0];
        out[((b*2+1)*HW+y)*HW+x] = d1*r2*lmg[1]+lmb[1];
    }
}

extern "C" void kernel_launch(void* const* d_in, const int* in_sizes, int n_in,
                              void* d_out, int out_size){
    const float* feat1=(const float*)d_in[0];  const float* feat2=(const float*)d_in[1];
    const float* feat3=(const float*)d_in[2];  const float* feat4=(const float*)d_in[3];
    const float* cls_w=(const float*)d_in[4];  const float* cls_b=(const float*)d_in[5];
    const float* cbn_g=(const float*)d_in[6];  const float* cbn_b=(const float*)d_in[7];
    const float* cbn_rm=(const float*)d_in[8]; const float* cbn_rv=(const float*)d_in[9];
    const float* pw1=(const float*)d_in[10];   const float* pb1=(const float*)d_in[11];
    const float* pbn_g=(const float*)d_in[12]; const float* pbn_b=(const float*)d_in[13];
    const float* pbn_rm=(const float*)d_in[14];const float* pbn_rv=(const float*)d_in[15];
    const float* pw2=(const float*)d_in[16];   const float* pb2=(const float*)d_in[17];
    const float* lnf_g=(const float*)d_in[18]; const float* lnf_b=(const float*)d_in[19];
    const float* lnm_g=(const float*)d_in[20]; const float* lnm_b=(const float*)d_in[21];
    const float* protos=(const float*)d_in[22];
    float* out = (float*)d_out;

    static int smem_set = 0;
    if (!smem_set){
        cudaFuncSetAttribute(gemm_u<0>, cudaFuncAttributeMaxDynamicSharedMemorySize, SMEM_DYN);
        cudaFuncSetAttribute(gemm_u<1>, cudaFuncAttributeMaxDynamicSharedMemorySize, SMEM_DYN);
        cudaFuncSetAttribute(gemm_u<2>, cudaFuncAttributeMaxDynamicSharedMemorySize, SMEM_DYN);
        smem_set = 1;
    }

    concat_kernel<<<(M_TOT*C0+255)/256, 256>>>(feat1, feat2, feat3, feat4);
    wino_w<<<(UCH+255)/256, 256>>>(cls_w);
    wino_in<<<(TCH6+255)/256, 256>>>();
    dim3 gw(5, NT6/BM, 64);   // (5,4,64) = 1280 CTAs
    gemm_u<0><<<gw, THR, SMEM_DYN>>>(nullptr);   // 4th launch: profiled
    prep_bn<<<3, 256>>>(cls_b, cbn_g, cbn_b, cbn_rm, cbn_rv, pb1, pbn_g, pbn_b, pbn_rm, pbn_rv);
    wino_out<<<(TCH6+255)/256, 256>>>();
    prep_w1x1<<<(UCH+255)/256, 256>>>(pw1, pw2);
    dim3 g1(5, M_TOT/BM, 1);    // (5,144)
    gemm_u<1><<<g1, THR, SMEM_DYN>>>(nullptr);
    gemm_u<2><<<g1, THR, SMEM_DYN>>>(pb2);
    prep_proto<<<NPROTO, 32>>>(protos);
    head_kernel<<<(M_TOT*32+255)/256, 256>>>(lnf_g, lnf_b, lnm_g, lnm_b, out);
    (void)in_sizes; (void)n_in; (void)out_size;
}